// round 10
// baseline (speedup 1.0000x reference)
#include <cuda_runtime.h>
#include <cuda_fp16.h>
#include <math.h>
#include <stdint.h>

#define CD   1024
#define CH   16
#define CFF  4096
#define CB   8
#define CN   1024
#define NTOK (CB*CN)   // 8192

// ---------------- scratch (no allocations allowed) ----------------
__device__ __half g_xn_h [NTOK*CD];
__device__ float  g_xn_f [NTOK*CD];
__device__ __half g_qkv_h[NTOK*3*CD];
__device__ __half g_ao_h [NTOK*CD];
__device__ float  g_x1_f [NTOK*CD];
__device__ __half g_x2_h [NTOK*CD];
__device__ float  g_x2_f [NTOK*CD];
__device__ __half g_h_h  [NTOK*CFF];
__device__ __half g_wq_h [3*CD*CD];
__device__ __half g_wo_h [CD*CD];
__device__ __half g_w1_h [CFF*CD];
__device__ __half g_w2_h [CD*CFF];

// ---------------- helpers ----------------
__device__ __forceinline__ uint32_t smem_u32(const void* p) {
    uint32_t a;
    asm("{ .reg .u64 t; cvta.to.shared.u64 t, %1; cvt.u32.u64 %0, t; }" : "=r"(a) : "l"(p));
    return a;
}
__device__ __forceinline__ void mma_f16(float* d, const uint32_t* a, const uint32_t* b) {
    asm volatile(
        "mma.sync.aligned.m16n8k16.row.col.f32.f16.f16.f32 "
        "{%0,%1,%2,%3},{%4,%5,%6,%7},{%8,%9},{%0,%1,%2,%3};"
        : "+f"(d[0]), "+f"(d[1]), "+f"(d[2]), "+f"(d[3])
        : "r"(a[0]), "r"(a[1]), "r"(a[2]), "r"(a[3]), "r"(b[0]), "r"(b[1]));
}
__device__ __forceinline__ void ldsm_x4(uint32_t* r, uint32_t addr) {
    asm volatile("ldmatrix.sync.aligned.m8n8.x4.shared.b16 {%0,%1,%2,%3}, [%4];"
        : "=r"(r[0]), "=r"(r[1]), "=r"(r[2]), "=r"(r[3]) : "r"(addr));
}
__device__ __forceinline__ void ldsm_x4_t(uint32_t* r, uint32_t addr) {
    asm volatile("ldmatrix.sync.aligned.m8n8.x4.trans.shared.b16 {%0,%1,%2,%3}, [%4];"
        : "=r"(r[0]), "=r"(r[1]), "=r"(r[2]), "=r"(r[3]) : "r"(addr));
}
__device__ __forceinline__ uint32_t h2u(__half2 h) { return *(uint32_t*)&h; }

// ---------------- fused fp16 rounding (all 4 weight tensors, 1 launch) ----------
#define NWQ4 (3*CD*CD/4)
#define NWO4 (CD*CD/4)
#define NW14 (CFF*CD/4)
#define NW24 (CD*CFF/4)
#define NALL4 (NWQ4 + NWO4 + NW14 + NW24)   // 3145728

__global__ void __launch_bounds__(256) round_all_k(
    const float4* __restrict__ wq, const float4* __restrict__ wo,
    const float4* __restrict__ w1, const float4* __restrict__ w2,
    uint2* __restrict__ oq, uint2* __restrict__ oo,
    uint2* __restrict__ o1, uint2* __restrict__ o2)
{
    int i = blockIdx.x * 256 + threadIdx.x;
    const float4* s; uint2* d; int j;
    if (i < NWQ4)                     { s = wq; d = oq; j = i; }
    else if (i < NWQ4 + NWO4)         { s = wo; d = oo; j = i - NWQ4; }
    else if (i < NWQ4 + NWO4 + NW14)  { s = w1; d = o1; j = i - NWQ4 - NWO4; }
    else                              { s = w2; d = o2; j = i - NWQ4 - NWO4 - NW14; }
    float4 v = s[j];
    uint2 o;
    o.x = h2u(__floats2half2_rn(v.x, v.y));
    o.y = h2u(__floats2half2_rn(v.z, v.w));
    d[j] = o;
}

// ---------------- LayerNorm: fp16 + fp32 outputs ----------------
__global__ void __launch_bounds__(256) layernorm_k(
    const float* __restrict__ x, const float* __restrict__ w,
    const float* __restrict__ b, __half* __restrict__ yh, float* __restrict__ yf)
{
    int row = blockIdx.x;
    int tid = threadIdx.x;
    const float4* xr = (const float4*)(x + (size_t)row * CD);
    float4 xv = xr[tid];
    float s  = xv.x + xv.y + xv.z + xv.w;
    float ss = xv.x*xv.x + xv.y*xv.y + xv.z*xv.z + xv.w*xv.w;
    #pragma unroll
    for (int o = 16; o; o >>= 1) {
        s  += __shfl_xor_sync(0xffffffffu, s,  o);
        ss += __shfl_xor_sync(0xffffffffu, ss, o);
    }
    __shared__ float sm1[8], sm2[8];
    if ((tid & 31) == 0) { sm1[tid >> 5] = s; sm2[tid >> 5] = ss; }
    __syncthreads();
    float ts = 0.f, tss = 0.f;
    #pragma unroll
    for (int i = 0; i < 8; i++) { ts += sm1[i]; tss += sm2[i]; }
    float mu   = ts * (1.0f / CD);
    float var  = tss * (1.0f / CD) - mu * mu;
    float rstd = rsqrtf(var + 1e-5f);
    float4 wv = ((const float4*)w)[tid];
    float4 bv = ((const float4*)b)[tid];
    float4 ov;
    ov.x = (xv.x - mu) * rstd * wv.x + bv.x;
    ov.y = (xv.y - mu) * rstd * wv.y + bv.y;
    ov.z = (xv.z - mu) * rstd * wv.z + bv.z;
    ov.w = (xv.w - mu) * rstd * wv.w + bv.w;
    ((float4*)(yf + (size_t)row * CD))[tid] = ov;
    uint2 oh;
    oh.x = h2u(__floats2half2_rn(ov.x, ov.y));
    oh.y = h2u(__floats2half2_rn(ov.z, ov.w));
    ((uint2*)(yh + (size_t)row * CD))[tid] = oh;
}

// ---------------- fp16 mma.sync NT GEMM, persistent CTAs, 2 CTAs/SM ----------------
// C[M,N] = A[M,K] * B[N,K]^T.  CTA tile 128x128, 8 warps (32x64 each),
// K-chunk 64, 3-stage cp.async; persistent tile loop with next-tile
// prologue issued BEFORE current epilogue (overlaps fill with stores).
#define NST     3
#define ROWB    144u
#define ATILE_B 18432u
#define ST_BYTE (2u*ATILE_B)
#define GSMEM   (NST*ST_BYTE)          // 110592

template<int EPI>
__global__ void __launch_bounds__(256, 2) gemm_mma(
    const __half* __restrict__ A, const __half* __restrict__ B,
    const float* __restrict__ bias, const float* __restrict__ res,
    void* __restrict__ Cv, int M, int N, int K)
{
    extern __shared__ char smc[];
    const uint32_t smb = smem_u32(smc);
    const int tid  = threadIdx.x;
    const int wid  = tid >> 5;
    const int lane = tid & 31;
    const int g = lane >> 2, c = lane & 3;
    const int wy = wid & 3, wx = wid >> 2;
    const int nch = K >> 6;
    const int ntx = N >> 7;
    const int ntiles = (M >> 7) * ntx;

    const int lr = tid >> 3, lj = tid & 7;
    const uint32_t adst0 = (uint32_t)lr * ROWB + (uint32_t)lj * 16u;
    const uint32_t bdst0 = ATILE_B + adst0;
    const size_t rstep = (size_t)32 * K;
    const uint32_t lrow  = (uint32_t)(lane & 15);
    const uint32_t lhalf = (uint32_t)(lane >> 4);

    int t = blockIdx.x;
    if (t >= ntiles) return;

    const __half* asrc0;
    const __half* bsrc0;
    {
        int m0 = (t / ntx) * 128, n0 = (t % ntx) * 128;
        asrc0 = A + (size_t)(m0 + lr) * K + lj * 8;
        bsrc0 = B + (size_t)(n0 + lr) * K + lj * 8;
    }
    // prologue for first tile
    #pragma unroll
    for (int p = 0; p < NST - 1; p++) {
        uint32_t sb = smb + p * ST_BYTE;
        #pragma unroll
        for (int i = 0; i < 4; i++) {
            asm volatile("cp.async.cg.shared.global [%0], [%1], 16;"
                :: "r"(sb + adst0 + i*4608u), "l"(asrc0 + i*rstep + p*64));
            asm volatile("cp.async.cg.shared.global [%0], [%1], 16;"
                :: "r"(sb + bdst0 + i*4608u), "l"(bsrc0 + i*rstep + p*64));
        }
        asm volatile("cp.async.commit_group;");
    }

    while (true) {
        float acc[2][8][4] = {};

        for (int ch = 0; ch < nch; ch++) {
            asm volatile("cp.async.wait_group %0;" :: "n"(NST - 2));
            __syncthreads();

            int ch2 = ch + NST - 1;
            if (ch2 < nch) {
                uint32_t sb = smb + (uint32_t)(ch2 % NST) * ST_BYTE;
                #pragma unroll
                for (int i = 0; i < 4; i++) {
                    asm volatile("cp.async.cg.shared.global [%0], [%1], 16;"
                        :: "r"(sb + adst0 + i*4608u), "l"(asrc0 + i*rstep + ch2*64));
                    asm volatile("cp.async.cg.shared.global [%0], [%1], 16;"
                        :: "r"(sb + bdst0 + i*4608u), "l"(bsrc0 + i*rstep + ch2*64));
                }
            }
            asm volatile("cp.async.commit_group;");

            const uint32_t stb   = smb + (uint32_t)(ch % NST) * ST_BYTE;
            const uint32_t abase = stb + (uint32_t)(wy * 32 + lrow) * ROWB + lhalf * 16u;
            const uint32_t bbase = stb + ATILE_B
                                 + (uint32_t)(wx * 64 + lrow) * ROWB + lhalf * 16u;

            #pragma unroll
            for (int ks = 0; ks < 4; ks++) {
                uint32_t koff = (uint32_t)ks * 32u;
                uint32_t af[2][4], bf[8][2];
                #pragma unroll
                for (int mf = 0; mf < 2; mf++)
                    ldsm_x4(af[mf], abase + (uint32_t)mf * (16u * ROWB) + koff);
                #pragma unroll
                for (int np = 0; np < 4; np++) {
                    uint32_t q[4];
                    ldsm_x4(q, bbase + (uint32_t)np * (16u * ROWB) + koff);
                    bf[2*np][0]   = q[0]; bf[2*np][1]   = q[2];
                    bf[2*np+1][0] = q[1]; bf[2*np+1][1] = q[3];
                }
                #pragma unroll
                for (int mf = 0; mf < 2; mf++)
                    #pragma unroll
                    for (int nf = 0; nf < 8; nf++)
                        mma_f16(acc[mf][nf], af[mf], bf[nf]);
            }
        }

        // save current tile coords for epilogue
        const int em0 = (t / ntx) * 128;
        const int en0 = (t % ntx) * 128;
        const int tn = t + gridDim.x;
        const bool more = (tn < ntiles);

        __syncthreads();   // all warps done reading smem of this tile
        if (more) {
            int m0 = (tn / ntx) * 128, n0 = (tn % ntx) * 128;
            asrc0 = A + (size_t)(m0 + lr) * K + lj * 8;
            bsrc0 = B + (size_t)(n0 + lr) * K + lj * 8;
            #pragma unroll
            for (int p = 0; p < NST - 1; p++) {
                uint32_t sb = smb + p * ST_BYTE;
                #pragma unroll
                for (int i = 0; i < 4; i++) {
                    asm volatile("cp.async.cg.shared.global [%0], [%1], 16;"
                        :: "r"(sb + adst0 + i*4608u), "l"(asrc0 + i*rstep + p*64));
                    asm volatile("cp.async.cg.shared.global [%0], [%1], 16;"
                        :: "r"(sb + bdst0 + i*4608u), "l"(bsrc0 + i*rstep + p*64));
                }
                asm volatile("cp.async.commit_group;");
            }
        }

        // epilogue (registers + global only; overlaps next-tile fill)
        const int mbase = em0 + wy * 32;
        const int nbase = en0 + wx * 64;
        #pragma unroll
        for (int mf = 0; mf < 2; mf++) {
            int r0 = mbase + mf * 16 + g;
            #pragma unroll
            for (int nf = 0; nf < 8; nf++) {
                int col = nbase + nf * 8 + c * 2;
                float v0 = acc[mf][nf][0], v1 = acc[mf][nf][1];
                float v2 = acc[mf][nf][2], v3 = acc[mf][nf][3];
                if (EPI >= 1) {
                    float b0 = bias[col], b1 = bias[col + 1];
                    v0 += b0; v1 += b1; v2 += b0; v3 += b1;
                }
                if (EPI == 1) {
                    float* C = (float*)Cv;
                    float2 r01 = *(const float2*)(res + (size_t)r0 * N + col);
                    float2 r23 = *(const float2*)(res + (size_t)(r0 + 8) * N + col);
                    *(float2*)(C + (size_t)r0 * N + col)       = make_float2(v0 + r01.x, v1 + r01.y);
                    *(float2*)(C + (size_t)(r0 + 8) * N + col) = make_float2(v2 + r23.x, v3 + r23.y);
                } else {
                    if (EPI == 2) {
                        v0 = v0 * normcdff(v0);
                        v1 = v1 * normcdff(v1);
                        v2 = v2 * normcdff(v2);
                        v3 = v3 * normcdff(v3);
                    }
                    __half* C = (__half*)Cv;
                    *(uint32_t*)(C + (size_t)r0 * N + col)       = h2u(__floats2half2_rn(v0, v1));
                    *(uint32_t*)(C + (size_t)(r0 + 8) * N + col) = h2u(__floats2half2_rn(v2, v3));
                }
            }
        }

        if (!more) break;
        t = tn;
    }
}

// ---------------- Flash attention, fp16 mma, q-tile 128, trans-V (R9) ----------------
#define FH_STR 72
#define FH_QS  0
#define FH_KS  (128*FH_STR)
#define FH_VS  (FH_KS + 64*FH_STR)
#define FH_PW  (FH_VS + 64*FH_STR)
#define FH_END (FH_PW + 8*16*FH_STR)
#define FSM_TOT (FH_END*2 + 256)

__global__ void __launch_bounds__(256) flashm_k(
    const __half* __restrict__ qkv, const int* __restrict__ ids,
    __half* __restrict__ o)
{
    extern __shared__ char smc[];
    __half* smh = (__half*)smc;
    __half* Qs  = smh + FH_QS;
    __half* Ks  = smh + FH_KS;
    __half* Vs  = smh + FH_VS;
    float*  mk  = (float*)(smc + FH_END*2);
    const uint32_t smb = smem_u32(smc);

    const int tid = threadIdx.x;
    const int wid = tid >> 5, lane = tid & 31;
    const int g = lane >> 2, c = lane & 3;
    const int qt = blockIdx.x, h = blockIdx.y, b = blockIdx.z;
    const int q0 = qt * 128;
    const size_t rstr = 3 * CD;

    for (int i = tid; i < 1024; i += 256) {
        int r = i >> 3, j = i & 7;
        *(uint4*)(Qs + r * FH_STR + j * 8) =
            *(const uint4*)(qkv + (size_t)(b*CN + q0 + r) * rstr + h*64 + j*8);
    }

    float oa[8][4] = {};
    float m0 = -1e30f, m1 = -1e30f, l0 = 0.f, l1 = 0.f;

    const uint32_t lrow  = (uint32_t)(lane & 15);
    const uint32_t lhalf = (uint32_t)(lane >> 4);
    const uint32_t qbase = smb + (uint32_t)(wid*16 + lrow) * 144u + lhalf * 16u;
    const uint32_t kbase = smb + (uint32_t)(FH_KS*2) + lrow * 144u + lhalf * 16u;
    const uint32_t vbase = smb + (uint32_t)(FH_VS*2) + lrow * 144u + lhalf * 16u;
    const uint32_t pbase = smb + (uint32_t)(FH_PW*2) + (uint32_t)wid * (16u*144u)
                         + lrow * 144u + lhalf * 16u;
    __half* Pw = smh + FH_PW + wid * 16 * FH_STR;

    for (int kt = 0; kt < 16; kt++) {
        int k0 = kt * 64;
        __syncthreads();
        for (int i = tid; i < 512; i += 256) {
            int r = i >> 3, j = i & 7;
            const __half* gk = qkv + (size_t)(b*CN + k0 + r) * rstr + CD + h*64 + j*8;
            *(uint4*)(Ks + r * FH_STR + j * 8) = *(const uint4*)gk;
            *(uint4*)(Vs + r * FH_STR + j * 8) = *(const uint4*)(gk + CD);
        }
        if (tid < 64) mk[tid] = -1.25e8f * (float)ids[b*CN + k0 + tid];
        __syncthreads();

        float sa[8][4] = {};
        #pragma unroll
        for (int ks = 0; ks < 4; ks++) {
            uint32_t koff = (uint32_t)ks * 32u;
            uint32_t a[4];
            ldsm_x4(a, qbase + koff);
            #pragma unroll
            for (int np = 0; np < 4; np++) {
                uint32_t q[4];
                ldsm_x4(q, kbase + (uint32_t)np * (16u*144u) + koff);
                uint32_t b0[2] = {q[0], q[2]}, b1[2] = {q[1], q[3]};
                mma_f16(sa[2*np],   a, b0);
                mma_f16(sa[2*np+1], a, b1);
            }
        }

        float rmax0 = -1e30f, rmax1 = -1e30f;
        #pragma unroll
        for (int nf = 0; nf < 8; nf++) {
            float mv0 = mk[nf*8 + 2*c], mv1 = mk[nf*8 + 2*c + 1];
            sa[nf][0] = sa[nf][0]*0.125f + mv0; sa[nf][1] = sa[nf][1]*0.125f + mv1;
            sa[nf][2] = sa[nf][2]*0.125f + mv0; sa[nf][3] = sa[nf][3]*0.125f + mv1;
            rmax0 = fmaxf(rmax0, fmaxf(sa[nf][0], sa[nf][1]));
            rmax1 = fmaxf(rmax1, fmaxf(sa[nf][2], sa[nf][3]));
        }
        rmax0 = fmaxf(rmax0, __shfl_xor_sync(0xffffffffu, rmax0, 1));
        rmax0 = fmaxf(rmax0, __shfl_xor_sync(0xffffffffu, rmax0, 2));
        rmax1 = fmaxf(rmax1, __shfl_xor_sync(0xffffffffu, rmax1, 1));
        rmax1 = fmaxf(rmax1, __shfl_xor_sync(0xffffffffu, rmax1, 2));
        float mn0 = fmaxf(m0, rmax0), mn1 = fmaxf(m1, rmax1);
        float al0 = __expf(m0 - mn0), al1 = __expf(m1 - mn1);
        m0 = mn0; m1 = mn1;
        float ps0 = 0.f, ps1 = 0.f;
        #pragma unroll
        for (int nf = 0; nf < 8; nf++) {
            float p0 = __expf(sa[nf][0] - mn0);
            float p1 = __expf(sa[nf][1] - mn0);
            float p2 = __expf(sa[nf][2] - mn1);
            float p3 = __expf(sa[nf][3] - mn1);
            ps0 += p0 + p1; ps1 += p2 + p3;
            *(uint32_t*)(Pw + g*FH_STR + nf*8 + 2*c)     = h2u(__floats2half2_rn(p0, p1));
            *(uint32_t*)(Pw + (g+8)*FH_STR + nf*8 + 2*c) = h2u(__floats2half2_rn(p2, p3));
        }
        ps0 += __shfl_xor_sync(0xffffffffu, ps0, 1);
        ps0 += __shfl_xor_sync(0xffffffffu, ps0, 2);
        ps1 += __shfl_xor_sync(0xffffffffu, ps1, 1);
        ps1 += __shfl_xor_sync(0xffffffffu, ps1, 2);
        l0 = l0 * al0 + ps0;
        l1 = l1 * al1 + ps1;
        #pragma unroll
        for (int nf = 0; nf < 8; nf++) {
            oa[nf][0] *= al0; oa[nf][1] *= al0;
            oa[nf][2] *= al1; oa[nf][3] *= al1;
        }
        __syncwarp();

        #pragma unroll
        for (int ks = 0; ks < 4; ks++) {
            uint32_t a[4];
            ldsm_x4(a, pbase + (uint32_t)ks * 32u);
            #pragma unroll
            for (int np = 0; np < 4; np++) {
                uint32_t q[4];
                ldsm_x4_t(q, vbase + (uint32_t)ks * (16u*144u) + (uint32_t)np * 32u);
                uint32_t b0[2] = {q[0], q[1]}, b1[2] = {q[2], q[3]};
                mma_f16(oa[2*np],   a, b0);
                mma_f16(oa[2*np+1], a, b1);
            }
        }
        __syncwarp();
    }

    float inv0 = 1.0f / l0, inv1 = 1.0f / l1;
    size_t r0 = (size_t)(b*CN + q0 + wid*16 + g) * CD + h*64;
    size_t r1 = (size_t)(b*CN + q0 + wid*16 + g + 8) * CD + h*64;
    #pragma unroll
    for (int nf = 0; nf < 8; nf++) {
        int col = nf*8 + 2*c;
        *(uint32_t*)(o + r0 + col) = h2u(__floats2half2_rn(oa[nf][0]*inv0, oa[nf][1]*inv0));
        *(uint32_t*)(o + r1 + col) = h2u(__floats2half2_rn(oa[nf][2]*inv1, oa[nf][3]*inv1));
    }
}

// ---------------- launch ----------------
static inline int persist_grid(int ntiles, int slots) {
    return ntiles < slots ? ntiles : slots;
}

extern "C" void kernel_launch(void* const* d_in, const int* in_sizes, int n_in,
                              void* d_out, int out_size)
{
    const float* x      = (const float*)d_in[0];
    const int*   ids    = (const int*)  d_in[1];
    const float* n1w    = (const float*)d_in[2];
    const float* n1b    = (const float*)d_in[3];
    const float* pin_w  = (const float*)d_in[4];
    const float* pout_w = (const float*)d_in[5];
    const float* pout_b = (const float*)d_in[6];
    const float* n2w    = (const float*)d_in[7];
    const float* n2b    = (const float*)d_in[8];
    const float* l1w    = (const float*)d_in[9];
    const float* l1b    = (const float*)d_in[10];
    const float* l2w    = (const float*)d_in[11];
    const float* l2b    = (const float*)d_in[12];
    float* out = (float*)d_out;

    __half *xnh, *qkvh, *aoh, *x2h, *hhh, *wqh, *woh, *w1h, *w2h;
    float *xnf, *x1f, *x2f;
    cudaGetSymbolAddress((void**)&xnh,  g_xn_h);
    cudaGetSymbolAddress((void**)&xnf,  g_xn_f);
    cudaGetSymbolAddress((void**)&qkvh, g_qkv_h);
    cudaGetSymbolAddress((void**)&aoh,  g_ao_h);
    cudaGetSymbolAddress((void**)&x1f,  g_x1_f);
    cudaGetSymbolAddress((void**)&x2h,  g_x2_h);
    cudaGetSymbolAddress((void**)&x2f,  g_x2_f);
    cudaGetSymbolAddress((void**)&hhh,  g_h_h);
    cudaGetSymbolAddress((void**)&wqh,  g_wq_h);
    cudaGetSymbolAddress((void**)&woh,  g_wo_h);
    cudaGetSymbolAddress((void**)&w1h,  g_w1_h);
    cudaGetSymbolAddress((void**)&w2h,  g_w2_h);

    int smCount = 148;
    cudaDeviceGetAttribute(&smCount, cudaDevAttrMultiProcessorCount, 0);
    const int slots = 2 * smCount;

    cudaFuncSetAttribute(flashm_k,    cudaFuncAttributeMaxDynamicSharedMemorySize, FSM_TOT);
    cudaFuncSetAttribute(gemm_mma<0>, cudaFuncAttributeMaxDynamicSharedMemorySize, GSMEM);
    cudaFuncSetAttribute(gemm_mma<1>, cudaFuncAttributeMaxDynamicSharedMemorySize, GSMEM);
    cudaFuncSetAttribute(gemm_mma<2>, cudaFuncAttributeMaxDynamicSharedMemorySize, GSMEM);

    // 0) weights -> fp16 (single fused launch)
    round_all_k<<<NALL4/256, 256>>>(
        (const float4*)pin_w, (const float4*)pout_w, (const float4*)l1w, (const float4*)l2w,
        (uint2*)wqh, (uint2*)woh, (uint2*)w1h, (uint2*)w2h);

    // 1) xn = LN1(x)
    layernorm_k<<<NTOK, 256>>>(x, n1w, n1b, xnh, xnf);
    // 2) qkv = xn @ Wq^T  (fp16 out)
    gemm_mma<0><<<persist_grid((3*CD/128)*(NTOK/128), slots), 256, GSMEM>>>(
        xnh, wqh, nullptr, nullptr, qkvh, NTOK, 3*CD, CD);
    // 3) flash attention -> ao (fp16)
    flashm_k<<<dim3(CN/128, CH, CB), 256, FSM_TOT>>>(qkvh, ids, aoh);
    // 4) x1 = ao @ Wo^T + bout + xn  (fp32 out)
    gemm_mma<1><<<persist_grid((CD/128)*(NTOK/128), slots), 256, GSMEM>>>(
        aoh, woh, pout_b, xnf, x1f, NTOK, CD, CD);
    // 5) x2 = LN2(x1)
    layernorm_k<<<NTOK, 256>>>(x1f, n2w, n2b, x2h, x2f);
    // 6) h = gelu(x2 @ W1^T + b1)  (fp16 out)
    gemm_mma<2><<<persist_grid((CFF/128)*(NTOK/128), slots), 256, GSMEM>>>(
        x2h, w1h, l1b, nullptr, hhh, NTOK, CFF, CD);
    // 7) out = h @ W2^T + b2 + x2  (fp32 out)
    gemm_mma<1><<<persist_grid((CD/128)*(NTOK/128), slots), 256, GSMEM>>>(
        hhh, w2h, l2b, x2f, out, NTOK, CD, CFF);
}

// round 11
// speedup vs baseline: 1.0585x; 1.0585x over previous
#include <cuda_runtime.h>
#include <cuda_fp16.h>
#include <math.h>
#include <stdint.h>

#define CD   1024
#define CH   16
#define CFF  4096
#define CB   8
#define CN   1024
#define NTOK (CB*CN)   // 8192

// ---------------- scratch (no allocations allowed) ----------------
__device__ __half g_xn_h [NTOK*CD];
__device__ float  g_xn_f [NTOK*CD];
__device__ __half g_qkv_h[NTOK*3*CD];
__device__ __half g_ao_h [NTOK*CD];
__device__ float  g_x1_f [NTOK*CD];
__device__ __half g_x2_h [NTOK*CD];
__device__ float  g_x2_f [NTOK*CD];
__device__ __half g_h_h  [NTOK*CFF];
__device__ __half g_wq_h [3*CD*CD];
__device__ __half g_wo_h [CD*CD];
__device__ __half g_w1_h [CFF*CD];
__device__ __half g_w2_h [CD*CFF];

// ---------------- helpers ----------------
__device__ __forceinline__ uint32_t smem_u32(const void* p) {
    uint32_t a;
    asm("{ .reg .u64 t; cvta.to.shared.u64 t, %1; cvt.u32.u64 %0, t; }" : "=r"(a) : "l"(p));
    return a;
}
__device__ __forceinline__ void mma_f16(float* d, const uint32_t* a, const uint32_t* b) {
    asm volatile(
        "mma.sync.aligned.m16n8k16.row.col.f32.f16.f16.f32 "
        "{%0,%1,%2,%3},{%4,%5,%6,%7},{%8,%9},{%0,%1,%2,%3};"
        : "+f"(d[0]), "+f"(d[1]), "+f"(d[2]), "+f"(d[3])
        : "r"(a[0]), "r"(a[1]), "r"(a[2]), "r"(a[3]), "r"(b[0]), "r"(b[1]));
}
__device__ __forceinline__ void ldsm_x4(uint32_t* r, uint32_t addr) {
    asm volatile("ldmatrix.sync.aligned.m8n8.x4.shared.b16 {%0,%1,%2,%3}, [%4];"
        : "=r"(r[0]), "=r"(r[1]), "=r"(r[2]), "=r"(r[3]) : "r"(addr));
}
__device__ __forceinline__ void ldsm_x4_t(uint32_t* r, uint32_t addr) {
    asm volatile("ldmatrix.sync.aligned.m8n8.x4.trans.shared.b16 {%0,%1,%2,%3}, [%4];"
        : "=r"(r[0]), "=r"(r[1]), "=r"(r[2]), "=r"(r[3]) : "r"(addr));
}
__device__ __forceinline__ uint32_t h2u(__half2 h) { return *(uint32_t*)&h; }

// ---------------- fused fp16 rounding (all 4 weight tensors, 1 launch) ----------
#define NWQ4 (3*CD*CD/4)
#define NWO4 (CD*CD/4)
#define NW14 (CFF*CD/4)
#define NW24 (CD*CFF/4)
#define NALL4 (NWQ4 + NWO4 + NW14 + NW24)

__global__ void __launch_bounds__(256) round_all_k(
    const float4* __restrict__ wq, const float4* __restrict__ wo,
    const float4* __restrict__ w1, const float4* __restrict__ w2,
    uint2* __restrict__ oq, uint2* __restrict__ oo,
    uint2* __restrict__ o1, uint2* __restrict__ o2)
{
    int i = blockIdx.x * 256 + threadIdx.x;
    const float4* s; uint2* d; int j;
    if (i < NWQ4)                     { s = wq; d = oq; j = i; }
    else if (i < NWQ4 + NWO4)         { s = wo; d = oo; j = i - NWQ4; }
    else if (i < NWQ4 + NWO4 + NW14)  { s = w1; d = o1; j = i - NWQ4 - NWO4; }
    else                              { s = w2; d = o2; j = i - NWQ4 - NWO4 - NW14; }
    float4 v = s[j];
    uint2 o;
    o.x = h2u(__floats2half2_rn(v.x, v.y));
    o.y = h2u(__floats2half2_rn(v.z, v.w));
    d[j] = o;
}

// ---------------- LayerNorm: fp16 + fp32 outputs ----------------
__global__ void __launch_bounds__(256) layernorm_k(
    const float* __restrict__ x, const float* __restrict__ w,
    const float* __restrict__ b, __half* __restrict__ yh, float* __restrict__ yf)
{
    int row = blockIdx.x;
    int tid = threadIdx.x;
    const float4* xr = (const float4*)(x + (size_t)row * CD);
    float4 xv = xr[tid];
    float s  = xv.x + xv.y + xv.z + xv.w;
    float ss = xv.x*xv.x + xv.y*xv.y + xv.z*xv.z + xv.w*xv.w;
    #pragma unroll
    for (int o = 16; o; o >>= 1) {
        s  += __shfl_xor_sync(0xffffffffu, s,  o);
        ss += __shfl_xor_sync(0xffffffffu, ss, o);
    }
    __shared__ float sm1[8], sm2[8];
    if ((tid & 31) == 0) { sm1[tid >> 5] = s; sm2[tid >> 5] = ss; }
    __syncthreads();
    float ts = 0.f, tss = 0.f;
    #pragma unroll
    for (int i = 0; i < 8; i++) { ts += sm1[i]; tss += sm2[i]; }
    float mu   = ts * (1.0f / CD);
    float var  = tss * (1.0f / CD) - mu * mu;
    float rstd = rsqrtf(var + 1e-5f);
    float4 wv = ((const float4*)w)[tid];
    float4 bv = ((const float4*)b)[tid];
    float4 ov;
    ov.x = (xv.x - mu) * rstd * wv.x + bv.x;
    ov.y = (xv.y - mu) * rstd * wv.y + bv.y;
    ov.z = (xv.z - mu) * rstd * wv.z + bv.z;
    ov.w = (xv.w - mu) * rstd * wv.w + bv.w;
    ((float4*)(yf + (size_t)row * CD))[tid] = ov;
    uint2 oh;
    oh.x = h2u(__floats2half2_rn(ov.x, ov.y));
    oh.y = h2u(__floats2half2_rn(ov.z, ov.w));
    ((uint2*)(yh + (size_t)row * CD))[tid] = oh;
}

// ---------------- fp16 mma.sync NT GEMM, 2 CTAs/SM (R9, proven) ----------------
#define NST     3
#define ROWB    144u
#define ATILE_B 18432u
#define ST_BYTE (2u*ATILE_B)
#define GSMEM   (NST*ST_BYTE)          // 110592

template<int EPI>
__global__ void __launch_bounds__(256, 2) gemm_mma(
    const __half* __restrict__ A, const __half* __restrict__ B,
    const float* __restrict__ bias, const float* __restrict__ res,
    void* __restrict__ Cv, int M, int N, int K)
{
    extern __shared__ char smc[];
    const uint32_t smb = smem_u32(smc);
    const int tid  = threadIdx.x;
    const int wid  = tid >> 5;
    const int lane = tid & 31;
    const int g = lane >> 2, c = lane & 3;
    const int wy = wid & 3, wx = wid >> 2;
    const int m0 = blockIdx.y * 128;
    const int n0 = blockIdx.x * 128;
    const int nch = K >> 6;

    const int lr = tid >> 3, lj = tid & 7;
    const __half* asrc0 = A + (size_t)(m0 + lr) * K + lj * 8;
    const __half* bsrc0 = B + (size_t)(n0 + lr) * K + lj * 8;
    const uint32_t adst0 = (uint32_t)lr * ROWB + (uint32_t)lj * 16u;
    const uint32_t bdst0 = ATILE_B + adst0;
    const size_t rstep = (size_t)32 * K;

    #pragma unroll
    for (int p = 0; p < NST - 1; p++) {
        uint32_t sb = smb + p * ST_BYTE;
        #pragma unroll
        for (int i = 0; i < 4; i++) {
            asm volatile("cp.async.cg.shared.global [%0], [%1], 16;"
                :: "r"(sb + adst0 + i*4608u), "l"(asrc0 + i*rstep + p*64));
            asm volatile("cp.async.cg.shared.global [%0], [%1], 16;"
                :: "r"(sb + bdst0 + i*4608u), "l"(bsrc0 + i*rstep + p*64));
        }
        asm volatile("cp.async.commit_group;");
    }

    float acc[2][8][4] = {};
    const uint32_t lrow  = (uint32_t)(lane & 15);
    const uint32_t lhalf = (uint32_t)(lane >> 4);

    for (int ch = 0; ch < nch; ch++) {
        asm volatile("cp.async.wait_group %0;" :: "n"(NST - 2));
        __syncthreads();

        int ch2 = ch + NST - 1;
        if (ch2 < nch) {
            uint32_t sb = smb + (uint32_t)(ch2 % NST) * ST_BYTE;
            #pragma unroll
            for (int i = 0; i < 4; i++) {
                asm volatile("cp.async.cg.shared.global [%0], [%1], 16;"
                    :: "r"(sb + adst0 + i*4608u), "l"(asrc0 + i*rstep + ch2*64));
                asm volatile("cp.async.cg.shared.global [%0], [%1], 16;"
                    :: "r"(sb + bdst0 + i*4608u), "l"(bsrc0 + i*rstep + ch2*64));
            }
        }
        asm volatile("cp.async.commit_group;");

        const uint32_t stb   = smb + (uint32_t)(ch % NST) * ST_BYTE;
        const uint32_t abase = stb + (uint32_t)(wy * 32 + lrow) * ROWB + lhalf * 16u;
        const uint32_t bbase = stb + ATILE_B
                             + (uint32_t)(wx * 64 + lrow) * ROWB + lhalf * 16u;

        #pragma unroll
        for (int ks = 0; ks < 4; ks++) {
            uint32_t koff = (uint32_t)ks * 32u;
            uint32_t af[2][4], bf[8][2];
            #pragma unroll
            for (int mf = 0; mf < 2; mf++)
                ldsm_x4(af[mf], abase + (uint32_t)mf * (16u * ROWB) + koff);
            #pragma unroll
            for (int np = 0; np < 4; np++) {
                uint32_t q[4];
                ldsm_x4(q, bbase + (uint32_t)np * (16u * ROWB) + koff);
                bf[2*np][0]   = q[0]; bf[2*np][1]   = q[2];
                bf[2*np+1][0] = q[1]; bf[2*np+1][1] = q[3];
            }
            #pragma unroll
            for (int mf = 0; mf < 2; mf++)
                #pragma unroll
                for (int nf = 0; nf < 8; nf++)
                    mma_f16(acc[mf][nf], af[mf], bf[nf]);
        }
    }

    const int mbase = m0 + wy * 32;
    const int nbase = n0 + wx * 64;
    #pragma unroll
    for (int mf = 0; mf < 2; mf++) {
        int r0 = mbase + mf * 16 + g;
        #pragma unroll
        for (int nf = 0; nf < 8; nf++) {
            int col = nbase + nf * 8 + c * 2;
            float v0 = acc[mf][nf][0], v1 = acc[mf][nf][1];
            float v2 = acc[mf][nf][2], v3 = acc[mf][nf][3];
            if (EPI >= 1) {
                float b0 = bias[col], b1 = bias[col + 1];
                v0 += b0; v1 += b1; v2 += b0; v3 += b1;
            }
            if (EPI == 1) {
                float* C = (float*)Cv;
                float2 r01 = *(const float2*)(res + (size_t)r0 * N + col);
                float2 r23 = *(const float2*)(res + (size_t)(r0 + 8) * N + col);
                *(float2*)(C + (size_t)r0 * N + col)       = make_float2(v0 + r01.x, v1 + r01.y);
                *(float2*)(C + (size_t)(r0 + 8) * N + col) = make_float2(v2 + r23.x, v3 + r23.y);
            } else {
                if (EPI == 2) {
                    v0 = v0 * normcdff(v0);
                    v1 = v1 * normcdff(v1);
                    v2 = v2 * normcdff(v2);
                    v3 = v3 * normcdff(v3);
                }
                __half* C = (__half*)Cv;
                *(uint32_t*)(C + (size_t)r0 * N + col)       = h2u(__floats2half2_rn(v0, v1));
                *(uint32_t*)(C + (size_t)(r0 + 8) * N + col) = h2u(__floats2half2_rn(v2, v3));
            }
        }
    }
}

// ---------------- Flash attention: q-tile 128, cp.async double-buffered K/V,
// Q fragments hoisted to registers ----------------
// smem halves (stride 72/row = 144B):
//   Qs[128][72] @0, K0/K1[64][72], V0/V1[64][72], Pw[8][16][72], mask float[2][64]
#define FH_STR 72
#define FH_QS  0
#define FH_K0  (128*FH_STR)                 // 9216
#define FH_K1  (FH_K0 + 64*FH_STR)          // 13824
#define FH_V0  (FH_K1 + 64*FH_STR)          // 18432
#define FH_V1  (FH_V0 + 64*FH_STR)          // 23040
#define FH_PW  (FH_V1 + 64*FH_STR)          // 27648
#define FH_END (FH_PW + 8*16*FH_STR)        // 36864 halves
#define FSM_TOT (FH_END*2 + 512)            // 74240 B

__global__ void __launch_bounds__(256, 2) flashm_k(
    const __half* __restrict__ qkv, const int* __restrict__ ids,
    __half* __restrict__ o)
{
    extern __shared__ char smc[];
    __half* smh = (__half*)smc;
    float*  mk  = (float*)(smc + FH_END*2);     // [2][64]
    const uint32_t smb = smem_u32(smc);

    const int tid = threadIdx.x;
    const int wid = tid >> 5, lane = tid & 31;
    const int g = lane >> 2, c = lane & 3;
    const int qt = blockIdx.x, h = blockIdx.y, b = blockIdx.z;
    const int q0 = qt * 128;
    const size_t rstr = 3 * CD;

    // per-thread K/V copy coords: 2 rows apart (512 uint4 over 256 threads)
    const int lr = tid >> 3, lj = tid & 7;              // rows lr, lr+32; 16B col lj
    const uint32_t kvoff = (uint32_t)lr * 144u + (uint32_t)lj * 16u;
    const __half* kvsrc = qkv + ((size_t)(b*CN + lr)) * rstr + CD + h*64 + lj*8;

    // load Q tile (synchronous; also covered by prologue wait)
    for (int i = tid; i < 1024; i += 256) {
        int r = i >> 3, j = i & 7;
        *(uint4*)(smh + FH_QS + r * FH_STR + j * 8) =
            *(const uint4*)(qkv + (size_t)(b*CN + q0 + r) * rstr + h*64 + j*8);
    }

    // prologue: async fill K/V stage 0 (kt=0) + mask 0
    {
        const __half* src = kvsrc;   // k0 = 0
        #pragma unroll
        for (int i = 0; i < 2; i++) {
            asm volatile("cp.async.cg.shared.global [%0], [%1], 16;"
                :: "r"(smb + FH_K0*2 + kvoff + i*4608u), "l"(src + (size_t)i*32*rstr));
            asm volatile("cp.async.cg.shared.global [%0], [%1], 16;"
                :: "r"(smb + FH_V0*2 + kvoff + i*4608u), "l"(src + (size_t)i*32*rstr + CD));
        }
        asm volatile("cp.async.commit_group;");
        if (tid < 64) mk[tid] = -1.25e8f * (float)ids[b*CN + tid];
    }
    __syncthreads();   // Q smem visible for fragment hoist

    // hoist Q fragments (loop-invariant)
    const uint32_t lrow  = (uint32_t)(lane & 15);
    const uint32_t lhalf = (uint32_t)(lane >> 4);
    uint32_t qf[4][4];
    {
        const uint32_t qbase = smb + (uint32_t)(wid*16 + lrow) * 144u + lhalf * 16u;
        #pragma unroll
        for (int ks = 0; ks < 4; ks++)
            ldsm_x4(qf[ks], qbase + (uint32_t)ks * 32u);
    }

    const uint32_t pbase = smb + (uint32_t)(FH_PW*2) + (uint32_t)wid * (16u*144u)
                         + lrow * 144u + lhalf * 16u;
    __half* Pw = smh + FH_PW + wid * 16 * FH_STR;

    float oa[8][4] = {};
    float m0 = -1e30f, m1 = -1e30f, l0 = 0.f, l1 = 0.f;

    for (int kt = 0; kt < 16; kt++) {
        const int cur = kt & 1;
        // issue next stage fill (buffer cur^1 was last read in iteration kt-1;
        // trailing __syncthreads of that iteration protects it)
        if (kt < 15) {
            const int k1 = (kt + 1) * 64;
            const __half* src = kvsrc + (size_t)k1 * rstr;
            const uint32_t kd = smb + (cur ? FH_K0 : FH_K1) * 2 + kvoff;
            const uint32_t vd = smb + (cur ? FH_V0 : FH_V1) * 2 + kvoff;
            #pragma unroll
            for (int i = 0; i < 2; i++) {
                asm volatile("cp.async.cg.shared.global [%0], [%1], 16;"
                    :: "r"(kd + i*4608u), "l"(src + (size_t)i*32*rstr));
                asm volatile("cp.async.cg.shared.global [%0], [%1], 16;"
                    :: "r"(vd + i*4608u), "l"(src + (size_t)i*32*rstr + CD));
            }
            if (tid < 64) mk[(cur^1)*64 + tid] = -1.25e8f * (float)ids[b*CN + k1 + tid];
        }
        asm volatile("cp.async.commit_group;");
        asm volatile("cp.async.wait_group 1;");
        __syncthreads();   // stage cur data + mask visible

        const uint32_t kbase = smb + (cur ? FH_K1 : FH_K0) * 2 + lrow * 144u + lhalf * 16u;
        const uint32_t vbase = smb + (cur ? FH_V1 : FH_V0) * 2 + lrow * 144u + lhalf * 16u;
        const float* mkc = mk + cur * 64;

        // ---- S = Q @ K^T ----
        float sa[8][4] = {};
        #pragma unroll
        for (int ks = 0; ks < 4; ks++) {
            #pragma unroll
            for (int np = 0; np < 4; np++) {
                uint32_t q[4];
                ldsm_x4(q, kbase + (uint32_t)np * (16u*144u) + (uint32_t)ks * 32u);
                uint32_t b0[2] = {q[0], q[2]}, b1[2] = {q[1], q[3]};
                mma_f16(sa[2*np],   qf[ks], b0);
                mma_f16(sa[2*np+1], qf[ks], b1);
            }
        }

        // ---- scale + mask + online softmax ----
        float rmax0 = -1e30f, rmax1 = -1e30f;
        #pragma unroll
        for (int nf = 0; nf < 8; nf++) {
            float mv0 = mkc[nf*8 + 2*c], mv1 = mkc[nf*8 + 2*c + 1];
            sa[nf][0] = sa[nf][0]*0.125f + mv0; sa[nf][1] = sa[nf][1]*0.125f + mv1;
            sa[nf][2] = sa[nf][2]*0.125f + mv0; sa[nf][3] = sa[nf][3]*0.125f + mv1;
            rmax0 = fmaxf(rmax0, fmaxf(sa[nf][0], sa[nf][1]));
            rmax1 = fmaxf(rmax1, fmaxf(sa[nf][2], sa[nf][3]));
        }
        rmax0 = fmaxf(rmax0, __shfl_xor_sync(0xffffffffu, rmax0, 1));
        rmax0 = fmaxf(rmax0, __shfl_xor_sync(0xffffffffu, rmax0, 2));
        rmax1 = fmaxf(rmax1, __shfl_xor_sync(0xffffffffu, rmax1, 1));
        rmax1 = fmaxf(rmax1, __shfl_xor_sync(0xffffffffu, rmax1, 2));
        float mn0 = fmaxf(m0, rmax0), mn1 = fmaxf(m1, rmax1);
        float al0 = __expf(m0 - mn0), al1 = __expf(m1 - mn1);
        m0 = mn0; m1 = mn1;
        float ps0 = 0.f, ps1 = 0.f;
        #pragma unroll
        for (int nf = 0; nf < 8; nf++) {
            float p0 = __expf(sa[nf][0] - mn0);
            float p1 = __expf(sa[nf][1] - mn0);
            float p2 = __expf(sa[nf][2] - mn1);
            float p3 = __expf(sa[nf][3] - mn1);
            ps0 += p0 + p1; ps1 += p2 + p3;
            *(uint32_t*)(Pw + g*FH_STR + nf*8 + 2*c)     = h2u(__floats2half2_rn(p0, p1));
            *(uint32_t*)(Pw + (g+8)*FH_STR + nf*8 + 2*c) = h2u(__floats2half2_rn(p2, p3));
        }
        ps0 += __shfl_xor_sync(0xffffffffu, ps0, 1);
        ps0 += __shfl_xor_sync(0xffffffffu, ps0, 2);
        ps1 += __shfl_xor_sync(0xffffffffu, ps1, 1);
        ps1 += __shfl_xor_sync(0xffffffffu, ps1, 2);
        l0 = l0 * al0 + ps0;
        l1 = l1 * al1 + ps1;
        #pragma unroll
        for (int nf = 0; nf < 8; nf++) {
            oa[nf][0] *= al0; oa[nf][1] *= al0;
            oa[nf][2] *= al1; oa[nf][3] *= al1;
        }
        __syncwarp();

        // ---- O += P @ V (trans-V fragments) ----
        #pragma unroll
        for (int ks = 0; ks < 4; ks++) {
            uint32_t a[4];
            ldsm_x4(a, pbase + (uint32_t)ks * 32u);
            #pragma unroll
            for (int np = 0; np < 4; np++) {
                uint32_t q[4];
                ldsm_x4_t(q, vbase + (uint32_t)ks * (16u*144u) + (uint32_t)np * 32u);
                uint32_t b0[2] = {q[0], q[1]}, b1[2] = {q[2], q[3]};
                mma_f16(oa[2*np],   a, b0);
                mma_f16(oa[2*np+1], a, b1);
            }
        }
        __syncthreads();   // protect buffer cur before its refill at kt+2
    }

    // ---- epilogue ----
    float inv0 = 1.0f / l0, inv1 = 1.0f / l1;
    size_t r0 = (size_t)(b*CN + q0 + wid*16 + g) * CD + h*64;
    size_t r1 = (size_t)(b*CN + q0 + wid*16 + g + 8) * CD + h*64;
    #pragma unroll
    for (int nf = 0; nf < 8; nf++) {
        int col = nf*8 + 2*c;
        *(uint32_t*)(o + r0 + col) = h2u(__floats2half2_rn(oa[nf][0]*inv0, oa[nf][1]*inv0));
        *(uint32_t*)(o + r1 + col) = h2u(__floats2half2_rn(oa[nf][2]*inv1, oa[nf][3]*inv1));
    }
}

// ---------------- launch ----------------
extern "C" void kernel_launch(void* const* d_in, const int* in_sizes, int n_in,
                              void* d_out, int out_size)
{
    const float* x      = (const float*)d_in[0];
    const int*   ids    = (const int*)  d_in[1];
    const float* n1w    = (const float*)d_in[2];
    const float* n1b    = (const float*)d_in[3];
    const float* pin_w  = (const float*)d_in[4];
    const float* pout_w = (const float*)d_in[5];
    const float* pout_b = (const float*)d_in[6];
    const float* n2w    = (const float*)d_in[7];
    const float* n2b    = (const float*)d_in[8];
    const float* l1w    = (const float*)d_in[9];
    const float* l1b    = (const float*)d_in[10];
    const float* l2w    = (const float*)d_in[11];
    const float* l2b    = (const float*)d_in[12];
    float* out = (float*)d_out;

    __half *xnh, *qkvh, *aoh, *x2h, *hhh, *wqh, *woh, *w1h, *w2h;
    float *xnf, *x1f, *x2f;
    cudaGetSymbolAddress((void**)&xnh,  g_xn_h);
    cudaGetSymbolAddress((void**)&xnf,  g_xn_f);
    cudaGetSymbolAddress((void**)&qkvh, g_qkv_h);
    cudaGetSymbolAddress((void**)&aoh,  g_ao_h);
    cudaGetSymbolAddress((void**)&x1f,  g_x1_f);
    cudaGetSymbolAddress((void**)&x2h,  g_x2_h);
    cudaGetSymbolAddress((void**)&x2f,  g_x2_f);
    cudaGetSymbolAddress((void**)&hhh,  g_h_h);
    cudaGetSymbolAddress((void**)&wqh,  g_wq_h);
    cudaGetSymbolAddress((void**)&woh,  g_wo_h);
    cudaGetSymbolAddress((void**)&w1h,  g_w1_h);
    cudaGetSymbolAddress((void**)&w2h,  g_w2_h);

    cudaFuncSetAttribute(flashm_k,    cudaFuncAttributeMaxDynamicSharedMemorySize, FSM_TOT);
    cudaFuncSetAttribute(gemm_mma<0>, cudaFuncAttributeMaxDynamicSharedMemorySize, GSMEM);
    cudaFuncSetAttribute(gemm_mma<1>, cudaFuncAttributeMaxDynamicSharedMemorySize, GSMEM);
    cudaFuncSetAttribute(gemm_mma<2>, cudaFuncAttributeMaxDynamicSharedMemorySize, GSMEM);

    // 0) weights -> fp16 (single fused launch)
    round_all_k<<<NALL4/256, 256>>>(
        (const float4*)pin_w, (const float4*)pout_w, (const float4*)l1w, (const float4*)l2w,
        (uint2*)wqh, (uint2*)woh, (uint2*)w1h, (uint2*)w2h);

    // 1) xn = LN1(x)
    layernorm_k<<<NTOK, 256>>>(x, n1w, n1b, xnh, xnf);
    // 2) qkv = xn @ Wq^T  (fp16 out)
    gemm_mma<0><<<dim3(3*CD/128, NTOK/128), 256, GSMEM>>>(xnh, wqh, nullptr, nullptr, qkvh, NTOK, 3*CD, CD);
    // 3) flash attention -> ao (fp16)
    flashm_k<<<dim3(CN/128, CH, CB), 256, FSM_TOT>>>(qkvh, ids, aoh);
    // 4) x1 = ao @ Wo^T + bout + xn  (fp32 out)
    gemm_mma<1><<<dim3(CD/128, NTOK/128), 256, GSMEM>>>(aoh, woh, pout_b, xnf, x1f, NTOK, CD, CD);
    // 5) x2 = LN2(x1)
    layernorm_k<<<NTOK, 256>>>(x1f, n2w, n2b, x2h, x2f);
    // 6) h = gelu(x2 @ W1^T + b1)  (fp16 out)
    gemm_mma<2><<<dim3(CFF/128, NTOK/128), 256, GSMEM>>>(x2h, w1h, l1b, nullptr, hhh, NTOK, CFF, CD);
    // 7) out = h @ W2^T + b2 + x2  (fp32 out)
    gemm_mma<1><<<dim3(CD/128, NTOK/128), 256, GSMEM>>>(hhh, w2h, l2b, x2f, out, NTOK, CD, CFF);
}

// round 12
// speedup vs baseline: 1.0710x; 1.0118x over previous
#include <cuda_runtime.h>
#include <cuda_fp16.h>
#include <math.h>
#include <stdint.h>

#define CD   1024
#define CH   16
#define CFF  4096
#define CB   8
#define CN   1024
#define NTOK (CB*CN)   // 8192

// ---------------- scratch (no allocations allowed) ----------------
__device__ __half g_xn_h [NTOK*CD];
__device__ float  g_xn_f [NTOK*CD];
__device__ __half g_qkv_h[NTOK*3*CD];
__device__ __half g_ao_h [NTOK*CD];
__device__ float  g_x1_f [NTOK*CD];
__device__ __half g_x2_h [NTOK*CD];
__device__ float  g_x2_f [NTOK*CD];
__device__ __half g_h_h  [NTOK*CFF];
__device__ __half g_wq_h [3*CD*CD];
__device__ __half g_wo_h [CD*CD];
__device__ __half g_w1_h [CFF*CD];
__device__ __half g_w2_h [CD*CFF];

// ---------------- helpers ----------------
__device__ __forceinline__ uint32_t smem_u32(const void* p) {
    uint32_t a;
    asm("{ .reg .u64 t; cvta.to.shared.u64 t, %1; cvt.u32.u64 %0, t; }" : "=r"(a) : "l"(p));
    return a;
}
__device__ __forceinline__ void mma_f16(float* d, const uint32_t* a, const uint32_t* b) {
    asm volatile(
        "mma.sync.aligned.m16n8k16.row.col.f32.f16.f16.f32 "
        "{%0,%1,%2,%3},{%4,%5,%6,%7},{%8,%9},{%0,%1,%2,%3};"
        : "+f"(d[0]), "+f"(d[1]), "+f"(d[2]), "+f"(d[3])
        : "r"(a[0]), "r"(a[1]), "r"(a[2]), "r"(a[3]), "r"(b[0]), "r"(b[1]));
}
__device__ __forceinline__ void ldsm_x4(uint32_t* r, uint32_t addr) {
    asm volatile("ldmatrix.sync.aligned.m8n8.x4.shared.b16 {%0,%1,%2,%3}, [%4];"
        : "=r"(r[0]), "=r"(r[1]), "=r"(r[2]), "=r"(r[3]) : "r"(addr));
}
__device__ __forceinline__ void ldsm_x4_t(uint32_t* r, uint32_t addr) {
    asm volatile("ldmatrix.sync.aligned.m8n8.x4.trans.shared.b16 {%0,%1,%2,%3}, [%4];"
        : "=r"(r[0]), "=r"(r[1]), "=r"(r[2]), "=r"(r[3]) : "r"(addr));
}
__device__ __forceinline__ uint32_t h2u(__half2 h) { return *(uint32_t*)&h; }

// ---------------- fused fp16 rounding (all 4 weight tensors, 1 launch) ----------
#define NWQ4 (3*CD*CD/4)
#define NWO4 (CD*CD/4)
#define NW14 (CFF*CD/4)
#define NW24 (CD*CFF/4)
#define NALL4 (NWQ4 + NWO4 + NW14 + NW24)

__global__ void __launch_bounds__(256) round_all_k(
    const float4* __restrict__ wq, const float4* __restrict__ wo,
    const float4* __restrict__ w1, const float4* __restrict__ w2,
    uint2* __restrict__ oq, uint2* __restrict__ oo,
    uint2* __restrict__ o1, uint2* __restrict__ o2)
{
    int i = blockIdx.x * 256 + threadIdx.x;
    const float4* s; uint2* d; int j;
    if (i < NWQ4)                     { s = wq; d = oq; j = i; }
    else if (i < NWQ4 + NWO4)         { s = wo; d = oo; j = i - NWQ4; }
    else if (i < NWQ4 + NWO4 + NW14)  { s = w1; d = o1; j = i - NWQ4 - NWO4; }
    else                              { s = w2; d = o2; j = i - NWQ4 - NWO4 - NW14; }
    float4 v = s[j];
    uint2 o;
    o.x = h2u(__floats2half2_rn(v.x, v.y));
    o.y = h2u(__floats2half2_rn(v.z, v.w));
    d[j] = o;
}

// ---------------- LayerNorm: fp16 + fp32 outputs ----------------
__global__ void __launch_bounds__(256) layernorm_k(
    const float* __restrict__ x, const float* __restrict__ w,
    const float* __restrict__ b, __half* __restrict__ yh, float* __restrict__ yf)
{
    int row = blockIdx.x;
    int tid = threadIdx.x;
    const float4* xr = (const float4*)(x + (size_t)row * CD);
    float4 xv = xr[tid];
    float s  = xv.x + xv.y + xv.z + xv.w;
    float ss = xv.x*xv.x + xv.y*xv.y + xv.z*xv.z + xv.w*xv.w;
    #pragma unroll
    for (int o = 16; o; o >>= 1) {
        s  += __shfl_xor_sync(0xffffffffu, s,  o);
        ss += __shfl_xor_sync(0xffffffffu, ss, o);
    }
    __shared__ float sm1[8], sm2[8];
    if ((tid & 31) == 0) { sm1[tid >> 5] = s; sm2[tid >> 5] = ss; }
    __syncthreads();
    float ts = 0.f, tss = 0.f;
    #pragma unroll
    for (int i = 0; i < 8; i++) { ts += sm1[i]; tss += sm2[i]; }
    float mu   = ts * (1.0f / CD);
    float var  = tss * (1.0f / CD) - mu * mu;
    float rstd = rsqrtf(var + 1e-5f);
    float4 wv = ((const float4*)w)[tid];
    float4 bv = ((const float4*)b)[tid];
    float4 ov;
    ov.x = (xv.x - mu) * rstd * wv.x + bv.x;
    ov.y = (xv.y - mu) * rstd * wv.y + bv.y;
    ov.z = (xv.z - mu) * rstd * wv.z + bv.z;
    ov.w = (xv.w - mu) * rstd * wv.w + bv.w;
    ((float4*)(yf + (size_t)row * CD))[tid] = ov;
    uint2 oh;
    oh.x = h2u(__floats2half2_rn(ov.x, ov.y));
    oh.y = h2u(__floats2half2_rn(ov.z, ov.w));
    ((uint2*)(yh + (size_t)row * CD))[tid] = oh;
}

// ---------------- fp16 mma.sync NT GEMM, 2 CTAs/SM (R9, proven) ----------------
#define NST     3
#define ROWB    144u
#define ATILE_B 18432u
#define ST_BYTE (2u*ATILE_B)
#define GSMEM   (NST*ST_BYTE)          // 110592

template<int EPI>
__global__ void __launch_bounds__(256, 2) gemm_mma(
    const __half* __restrict__ A, const __half* __restrict__ B,
    const float* __restrict__ bias, const float* __restrict__ res,
    void* __restrict__ Cv, int M, int N, int K)
{
    extern __shared__ char smc[];
    const uint32_t smb = smem_u32(smc);
    const int tid  = threadIdx.x;
    const int wid  = tid >> 5;
    const int lane = tid & 31;
    const int g = lane >> 2, c = lane & 3;
    const int wy = wid & 3, wx = wid >> 2;
    const int m0 = blockIdx.y * 128;
    const int n0 = blockIdx.x * 128;
    const int nch = K >> 6;

    const int lr = tid >> 3, lj = tid & 7;
    const __half* asrc0 = A + (size_t)(m0 + lr) * K + lj * 8;
    const __half* bsrc0 = B + (size_t)(n0 + lr) * K + lj * 8;
    const uint32_t adst0 = (uint32_t)lr * ROWB + (uint32_t)lj * 16u;
    const uint32_t bdst0 = ATILE_B + adst0;
    const size_t rstep = (size_t)32 * K;

    #pragma unroll
    for (int p = 0; p < NST - 1; p++) {
        uint32_t sb = smb + p * ST_BYTE;
        #pragma unroll
        for (int i = 0; i < 4; i++) {
            asm volatile("cp.async.cg.shared.global [%0], [%1], 16;"
                :: "r"(sb + adst0 + i*4608u), "l"(asrc0 + i*rstep + p*64));
            asm volatile("cp.async.cg.shared.global [%0], [%1], 16;"
                :: "r"(sb + bdst0 + i*4608u), "l"(bsrc0 + i*rstep + p*64));
        }
        asm volatile("cp.async.commit_group;");
    }

    float acc[2][8][4] = {};
    const uint32_t lrow  = (uint32_t)(lane & 15);
    const uint32_t lhalf = (uint32_t)(lane >> 4);

    for (int ch = 0; ch < nch; ch++) {
        asm volatile("cp.async.wait_group %0;" :: "n"(NST - 2));
        __syncthreads();

        int ch2 = ch + NST - 1;
        if (ch2 < nch) {
            uint32_t sb = smb + (uint32_t)(ch2 % NST) * ST_BYTE;
            #pragma unroll
            for (int i = 0; i < 4; i++) {
                asm volatile("cp.async.cg.shared.global [%0], [%1], 16;"
                    :: "r"(sb + adst0 + i*4608u), "l"(asrc0 + i*rstep + ch2*64));
                asm volatile("cp.async.cg.shared.global [%0], [%1], 16;"
                    :: "r"(sb + bdst0 + i*4608u), "l"(bsrc0 + i*rstep + ch2*64));
            }
        }
        asm volatile("cp.async.commit_group;");

        const uint32_t stb   = smb + (uint32_t)(ch % NST) * ST_BYTE;
        const uint32_t abase = stb + (uint32_t)(wy * 32 + lrow) * ROWB + lhalf * 16u;
        const uint32_t bbase = stb + ATILE_B
                             + (uint32_t)(wx * 64 + lrow) * ROWB + lhalf * 16u;

        #pragma unroll
        for (int ks = 0; ks < 4; ks++) {
            uint32_t koff = (uint32_t)ks * 32u;
            uint32_t af[2][4], bf[8][2];
            #pragma unroll
            for (int mf = 0; mf < 2; mf++)
                ldsm_x4(af[mf], abase + (uint32_t)mf * (16u * ROWB) + koff);
            #pragma unroll
            for (int np = 0; np < 4; np++) {
                uint32_t q[4];
                ldsm_x4(q, bbase + (uint32_t)np * (16u * ROWB) + koff);
                bf[2*np][0]   = q[0]; bf[2*np][1]   = q[2];
                bf[2*np+1][0] = q[1]; bf[2*np+1][1] = q[3];
            }
            #pragma unroll
            for (int mf = 0; mf < 2; mf++)
                #pragma unroll
                for (int nf = 0; nf < 8; nf++)
                    mma_f16(acc[mf][nf], af[mf], bf[nf]);
        }
    }

    const int mbase = m0 + wy * 32;
    const int nbase = n0 + wx * 64;
    #pragma unroll
    for (int mf = 0; mf < 2; mf++) {
        int r0 = mbase + mf * 16 + g;
        #pragma unroll
        for (int nf = 0; nf < 8; nf++) {
            int col = nbase + nf * 8 + c * 2;
            float v0 = acc[mf][nf][0], v1 = acc[mf][nf][1];
            float v2 = acc[mf][nf][2], v3 = acc[mf][nf][3];
            if (EPI >= 1) {
                float b0 = bias[col], b1 = bias[col + 1];
                v0 += b0; v1 += b1; v2 += b0; v3 += b1;
            }
            if (EPI == 1) {
                float* C = (float*)Cv;
                float2 r01 = *(const float2*)(res + (size_t)r0 * N + col);
                float2 r23 = *(const float2*)(res + (size_t)(r0 + 8) * N + col);
                *(float2*)(C + (size_t)r0 * N + col)       = make_float2(v0 + r01.x, v1 + r01.y);
                *(float2*)(C + (size_t)(r0 + 8) * N + col) = make_float2(v2 + r23.x, v3 + r23.y);
            } else {
                if (EPI == 2) {
                    v0 = v0 * normcdff(v0);
                    v1 = v1 * normcdff(v1);
                    v2 = v2 * normcdff(v2);
                    v3 = v3 * normcdff(v3);
                }
                __half* C = (__half*)Cv;
                *(uint32_t*)(C + (size_t)r0 * N + col)       = h2u(__floats2half2_rn(v0, v1));
                *(uint32_t*)(C + (size_t)(r0 + 8) * N + col) = h2u(__floats2half2_rn(v2, v3));
            }
        }
    }
}

// ---------------- Flash attention: q-tile 128, 3-stage cp.async K/V ring,
// Q fragments hoisted, single __syncthreads per kt-iteration ----------------
// smem halves (stride 72/row = 144B):
//   Qs[128][72] @0, K0..K2[64][72], V0..V2[64][72], Pw[8][16][72], mask float[3][64]
#define FH_STR 72
#define FH_QS  0
#define FH_K0  (128*FH_STR)                 // 9216
#define FH_V0  (FH_K0 + 3*64*FH_STR)        // 23040
#define FH_PW  (FH_V0 + 3*64*FH_STR)        // 36864
#define FH_END (FH_PW + 8*16*FH_STR)        // 46080 halves = 92160 B
#define FSM_TOT (FH_END*2 + 768)            // 92928 B

__global__ void __launch_bounds__(256, 2) flashm_k(
    const __half* __restrict__ qkv, const int* __restrict__ ids,
    __half* __restrict__ o)
{
    extern __shared__ char smc[];
    __half* smh = (__half*)smc;
    float*  mk  = (float*)(smc + FH_END*2);     // [3][64]
    const uint32_t smb = smem_u32(smc);

    const int tid = threadIdx.x;
    const int wid = tid >> 5, lane = tid & 31;
    const int g = lane >> 2, c = lane & 3;
    const int qt = blockIdx.x, h = blockIdx.y, b = blockIdx.z;
    const int q0 = qt * 128;
    const size_t rstr = 3 * CD;

    // per-thread K/V copy coords (512 uint4 over 256 threads: rows lr, lr+32)
    const int lr = tid >> 3, lj = tid & 7;
    const uint32_t kvoff = (uint32_t)lr * 144u + (uint32_t)lj * 16u;
    const __half* kvsrc = qkv + ((size_t)(b*CN + lr)) * rstr + CD + h*64 + lj*8;

    // load Q tile (synchronous)
    for (int i = tid; i < 1024; i += 256) {
        int r = i >> 3, j = i & 7;
        *(uint4*)(smh + FH_QS + r * FH_STR + j * 8) =
            *(const uint4*)(qkv + (size_t)(b*CN + q0 + r) * rstr + h*64 + j*8);
    }

    // prologue: async fill stages 0,1 (kt=0,1) + masks
    #pragma unroll
    for (int p = 0; p < 2; p++) {
        const __half* src = kvsrc + (size_t)(p * 64) * rstr;
        const uint32_t kd = smb + (FH_K0 + p*4608)*2 + kvoff;
        const uint32_t vd = smb + (FH_V0 + p*4608)*2 + kvoff;
        #pragma unroll
        for (int i = 0; i < 2; i++) {
            asm volatile("cp.async.cg.shared.global [%0], [%1], 16;"
                :: "r"(kd + i*4608u), "l"(src + (size_t)i*32*rstr));
            asm volatile("cp.async.cg.shared.global [%0], [%1], 16;"
                :: "r"(vd + i*4608u), "l"(src + (size_t)i*32*rstr + CD));
        }
        asm volatile("cp.async.commit_group;");
        if (tid < 64) mk[p*64 + tid] = -1.25e8f * (float)ids[b*CN + p*64 + tid];
    }
    __syncthreads();   // Q smem visible for fragment hoist

    // hoist Q fragments (loop-invariant)
    const uint32_t lrow  = (uint32_t)(lane & 15);
    const uint32_t lhalf = (uint32_t)(lane >> 4);
    uint32_t qf[4][4];
    {
        const uint32_t qbase = smb + (uint32_t)(wid*16 + lrow) * 144u + lhalf * 16u;
        #pragma unroll
        for (int ks = 0; ks < 4; ks++)
            ldsm_x4(qf[ks], qbase + (uint32_t)ks * 32u);
    }

    // per-stage ldmatrix base addresses (hoisted)
    uint32_t kb[3], vb[3];
    #pragma unroll
    for (int s = 0; s < 3; s++) {
        kb[s] = smb + (uint32_t)(FH_K0 + s*4608)*2 + lrow * 144u + lhalf * 16u;
        vb[s] = smb + (uint32_t)(FH_V0 + s*4608)*2 + lrow * 144u + lhalf * 16u;
    }
    const uint32_t pbase = smb + (uint32_t)(FH_PW*2) + (uint32_t)wid * (16u*144u)
                         + lrow * 144u + lhalf * 16u;
    __half* Pw = smh + FH_PW + wid * 16 * FH_STR;

    float oa[8][4] = {};
    float m0 = -1e30f, m1 = -1e30f, l0 = 0.f, l1 = 0.f;

    int st = 0;                       // stage index kt % 3
    for (int kt = 0; kt < 16; kt++) {
        // stage kt complete (leave stage kt+1 in flight)
        asm volatile("cp.async.wait_group 1;");
        __syncthreads();   // data + mask of stage st visible; stage (kt+2)%3 free

        // issue stage kt+2 fill (slot last read at kt-1, protected by sync above)
        if (kt < 14) {
            const int s2 = (st + 2 >= 3) ? st - 1 : st + 2;
            const int k2 = (kt + 2) * 64;
            const __half* src = kvsrc + (size_t)k2 * rstr;
            const uint32_t kd = kb[s2] - (lrow * 144u + lhalf * 16u) + kvoff;
            const uint32_t vd = vb[s2] - (lrow * 144u + lhalf * 16u) + kvoff;
            #pragma unroll
            for (int i = 0; i < 2; i++) {
                asm volatile("cp.async.cg.shared.global [%0], [%1], 16;"
                    :: "r"(kd + i*4608u), "l"(src + (size_t)i*32*rstr));
                asm volatile("cp.async.cg.shared.global [%0], [%1], 16;"
                    :: "r"(vd + i*4608u), "l"(src + (size_t)i*32*rstr + CD));
            }
            if (tid < 64) mk[s2*64 + tid] = -1.25e8f * (float)ids[b*CN + k2 + tid];
        }
        asm volatile("cp.async.commit_group;");

        const uint32_t kbase = kb[st];
        const uint32_t vbase = vb[st];
        const float* mkc = mk + st * 64;

        // ---- S = Q @ K^T ----
        float sa[8][4] = {};
        #pragma unroll
        for (int ks = 0; ks < 4; ks++) {
            #pragma unroll
            for (int np = 0; np < 4; np++) {
                uint32_t q[4];
                ldsm_x4(q, kbase + (uint32_t)np * (16u*144u) + (uint32_t)ks * 32u);
                uint32_t b0[2] = {q[0], q[2]}, b1[2] = {q[1], q[3]};
                mma_f16(sa[2*np],   qf[ks], b0);
                mma_f16(sa[2*np+1], qf[ks], b1);
            }
        }

        // ---- scale + mask + online softmax ----
        float rmax0 = -1e30f, rmax1 = -1e30f;
        #pragma unroll
        for (int nf = 0; nf < 8; nf++) {
            float mv0 = mkc[nf*8 + 2*c], mv1 = mkc[nf*8 + 2*c + 1];
            sa[nf][0] = sa[nf][0]*0.125f + mv0; sa[nf][1] = sa[nf][1]*0.125f + mv1;
            sa[nf][2] = sa[nf][2]*0.125f + mv0; sa[nf][3] = sa[nf][3]*0.125f + mv1;
            rmax0 = fmaxf(rmax0, fmaxf(sa[nf][0], sa[nf][1]));
            rmax1 = fmaxf(rmax1, fmaxf(sa[nf][2], sa[nf][3]));
        }
        rmax0 = fmaxf(rmax0, __shfl_xor_sync(0xffffffffu, rmax0, 1));
        rmax0 = fmaxf(rmax0, __shfl_xor_sync(0xffffffffu, rmax0, 2));
        rmax1 = fmaxf(rmax1, __shfl_xor_sync(0xffffffffu, rmax1, 1));
        rmax1 = fmaxf(rmax1, __shfl_xor_sync(0xffffffffu, rmax1, 2));
        float mn0 = fmaxf(m0, rmax0), mn1 = fmaxf(m1, rmax1);
        float al0 = __expf(m0 - mn0), al1 = __expf(m1 - mn1);
        m0 = mn0; m1 = mn1;
        float ps0 = 0.f, ps1 = 0.f;
        #pragma unroll
        for (int nf = 0; nf < 8; nf++) {
            float p0 = __expf(sa[nf][0] - mn0);
            float p1 = __expf(sa[nf][1] - mn0);
            float p2 = __expf(sa[nf][2] - mn1);
            float p3 = __expf(sa[nf][3] - mn1);
            ps0 += p0 + p1; ps1 += p2 + p3;
            *(uint32_t*)(Pw + g*FH_STR + nf*8 + 2*c)     = h2u(__floats2half2_rn(p0, p1));
            *(uint32_t*)(Pw + (g+8)*FH_STR + nf*8 + 2*c) = h2u(__floats2half2_rn(p2, p3));
        }
        ps0 += __shfl_xor_sync(0xffffffffu, ps0, 1);
        ps0 += __shfl_xor_sync(0xffffffffu, ps0, 2);
        ps1 += __shfl_xor_sync(0xffffffffu, ps1, 1);
        ps1 += __shfl_xor_sync(0xffffffffu, ps1, 2);
        l0 = l0 * al0 + ps0;
        l1 = l1 * al1 + ps1;
        #pragma unroll
        for (int nf = 0; nf < 8; nf++) {
            oa[nf][0] *= al0; oa[nf][1] *= al0;
            oa[nf][2] *= al1; oa[nf][3] *= al1;
        }
        __syncwarp();

        // ---- O += P @ V (trans-V fragments) ----
        #pragma unroll
        for (int ks = 0; ks < 4; ks++) {
            uint32_t a[4];
            ldsm_x4(a, pbase + (uint32_t)ks * 32u);
            #pragma unroll
            for (int np = 0; np < 4; np++) {
                uint32_t q[4];
                ldsm_x4_t(q, vbase + (uint32_t)ks * (16u*144u) + (uint32_t)np * 32u);
                uint32_t b0[2] = {q[0], q[1]}, b1[2] = {q[2], q[3]};
                mma_f16(oa[2*np],   a, b0);
                mma_f16(oa[2*np+1], a, b1);
            }
        }
        __syncwarp();

        st = (st + 1 >= 3) ? 0 : st + 1;
    }

    // ---- epilogue ----
    float inv0 = 1.0f / l0, inv1 = 1.0f / l1;
    size_t r0 = (size_t)(b*CN + q0 + wid*16 + g) * CD + h*64;
    size_t r1 = (size_t)(b*CN + q0 + wid*16 + g + 8) * CD + h*64;
    #pragma unroll
    for (int nf = 0; nf < 8; nf++) {
        int col = nf*8 + 2*c;
        *(uint32_t*)(o + r0 + col) = h2u(__floats2half2_rn(oa[nf][0]*inv0, oa[nf][1]*inv0));
        *(uint32_t*)(o + r1 + col) = h2u(__floats2half2_rn(oa[nf][2]*inv1, oa[nf][3]*inv1));
    }
}

// ---------------- launch ----------------
extern "C" void kernel_launch(void* const* d_in, const int* in_sizes, int n_in,
                              void* d_out, int out_size)
{
    const float* x      = (const float*)d_in[0];
    const int*   ids    = (const int*)  d_in[1];
    const float* n1w    = (const float*)d_in[2];
    const float* n1b    = (const float*)d_in[3];
    const float* pin_w  = (const float*)d_in[4];
    const float* pout_w = (const float*)d_in[5];
    const float* pout_b = (const float*)d_in[6];
    const float* n2w    = (const float*)d_in[7];
    const float* n2b    = (const float*)d_in[8];
    const float* l1w    = (const float*)d_in[9];
    const float* l1b    = (const float*)d_in[10];
    const float* l2w    = (const float*)d_in[11];
    const float* l2b    = (const float*)d_in[12];
    float* out = (float*)d_out;

    __half *xnh, *qkvh, *aoh, *x2h, *hhh, *wqh, *woh, *w1h, *w2h;
    float *xnf, *x1f, *x2f;
    cudaGetSymbolAddress((void**)&xnh,  g_xn_h);
    cudaGetSymbolAddress((void**)&xnf,  g_xn_f);
    cudaGetSymbolAddress((void**)&qkvh, g_qkv_h);
    cudaGetSymbolAddress((void**)&aoh,  g_ao_h);
    cudaGetSymbolAddress((void**)&x1f,  g_x1_f);
    cudaGetSymbolAddress((void**)&x2h,  g_x2_h);
    cudaGetSymbolAddress((void**)&x2f,  g_x2_f);
    cudaGetSymbolAddress((void**)&hhh,  g_h_h);
    cudaGetSymbolAddress((void**)&wqh,  g_wq_h);
    cudaGetSymbolAddress((void**)&woh,  g_wo_h);
    cudaGetSymbolAddress((void**)&w1h,  g_w1_h);
    cudaGetSymbolAddress((void**)&w2h,  g_w2_h);

    cudaFuncSetAttribute(flashm_k,    cudaFuncAttributeMaxDynamicSharedMemorySize, FSM_TOT);
    cudaFuncSetAttribute(gemm_mma<0>, cudaFuncAttributeMaxDynamicSharedMemorySize, GSMEM);
    cudaFuncSetAttribute(gemm_mma<1>, cudaFuncAttributeMaxDynamicSharedMemorySize, GSMEM);
    cudaFuncSetAttribute(gemm_mma<2>, cudaFuncAttributeMaxDynamicSharedMemorySize, GSMEM);

    // 0) weights -> fp16 (single fused launch)
    round_all_k<<<NALL4/256, 256>>>(
        (const float4*)pin_w, (const float4*)pout_w, (const float4*)l1w, (const float4*)l2w,
        (uint2*)wqh, (uint2*)woh, (uint2*)w1h, (uint2*)w2h);

    // 1) xn = LN1(x)
    layernorm_k<<<NTOK, 256>>>(x, n1w, n1b, xnh, xnf);
    // 2) qkv = xn @ Wq^T  (fp16 out)
    gemm_mma<0><<<dim3(3*CD/128, NTOK/128), 256, GSMEM>>>(xnh, wqh, nullptr, nullptr, qkvh, NTOK, 3*CD, CD);
    // 3) flash attention -> ao (fp16)
    flashm_k<<<dim3(CN/128, CH, CB), 256, FSM_TOT>>>(qkvh, ids, aoh);
    // 4) x1 = ao @ Wo^T + bout + xn  (fp32 out)
    gemm_mma<1><<<dim3(CD/128, NTOK/128), 256, GSMEM>>>(aoh, woh, pout_b, xnf, x1f, NTOK, CD, CD);
    // 5) x2 = LN2(x1)
    layernorm_k<<<NTOK, 256>>>(x1f, n2w, n2b, x2h, x2f);
    // 6) h = gelu(x2 @ W1^T + b1)  (fp16 out)
    gemm_mma<2><<<dim3(CFF/128, NTOK/128), 256, GSMEM>>>(x2h, w1h, l1b, nullptr, hhh, NTOK, CFF, CD);
    // 7) out = h @ W2^T + b2 + x2  (fp32 out)
    gemm_mma<1><<<dim3(CD/128, NTOK/128), 256, GSMEM>>>(hhh, w2h, l2b, x2f, out, NTOK, CD, CFF);
}

// round 13
// speedup vs baseline: 1.0796x; 1.0081x over previous
#include <cuda_runtime.h>
#include <cuda_fp16.h>
#include <math.h>
#include <stdint.h>

#define CD   1024
#define CH   16
#define CFF  4096
#define CB   8
#define CN   1024
#define NTOK (CB*CN)   // 8192

// ---------------- scratch (no allocations allowed) ----------------
__device__ __half g_xn_h [NTOK*CD];
__device__ float  g_xn_f [NTOK*CD];
__device__ __half g_qkv_h[NTOK*3*CD];
__device__ __half g_ao_h [NTOK*CD];
__device__ float  g_x1_f [NTOK*CD];
__device__ __half g_x2_h [NTOK*CD];
__device__ float  g_x2_f [NTOK*CD];
__device__ __half g_h_h  [NTOK*CFF];
__device__ __half g_wq_h [3*CD*CD];
__device__ __half g_wo_h [CD*CD];
__device__ __half g_w1_h [CFF*CD];
__device__ __half g_w2_h [CD*CFF];

// ---------------- helpers ----------------
__device__ __forceinline__ uint32_t smem_u32(const void* p) {
    uint32_t a;
    asm("{ .reg .u64 t; cvta.to.shared.u64 t, %1; cvt.u32.u64 %0, t; }" : "=r"(a) : "l"(p));
    return a;
}
__device__ __forceinline__ void mma_f16(float* d, const uint32_t* a, const uint32_t* b) {
    asm volatile(
        "mma.sync.aligned.m16n8k16.row.col.f32.f16.f16.f32 "
        "{%0,%1,%2,%3},{%4,%5,%6,%7},{%8,%9},{%0,%1,%2,%3};"
        : "+f"(d[0]), "+f"(d[1]), "+f"(d[2]), "+f"(d[3])
        : "r"(a[0]), "r"(a[1]), "r"(a[2]), "r"(a[3]), "r"(b[0]), "r"(b[1]));
}
__device__ __forceinline__ void ldsm_x4(uint32_t* r, uint32_t addr) {
    asm volatile("ldmatrix.sync.aligned.m8n8.x4.shared.b16 {%0,%1,%2,%3}, [%4];"
        : "=r"(r[0]), "=r"(r[1]), "=r"(r[2]), "=r"(r[3]) : "r"(addr));
}
__device__ __forceinline__ void ldsm_x4_t(uint32_t* r, uint32_t addr) {
    asm volatile("ldmatrix.sync.aligned.m8n8.x4.trans.shared.b16 {%0,%1,%2,%3}, [%4];"
        : "=r"(r[0]), "=r"(r[1]), "=r"(r[2]), "=r"(r[3]) : "r"(addr));
}
__device__ __forceinline__ uint32_t h2u(__half2 h) { return *(uint32_t*)&h; }

// ---------------- fused fp16 rounding (all 4 weight tensors, 1 launch) ----------
#define NWQ4 (3*CD*CD/4)
#define NWO4 (CD*CD/4)
#define NW14 (CFF*CD/4)
#define NW24 (CD*CFF/4)
#define NALL4 (NWQ4 + NWO4 + NW14 + NW24)

__global__ void __launch_bounds__(256) round_all_k(
    const float4* __restrict__ wq, const float4* __restrict__ wo,
    const float4* __restrict__ w1, const float4* __restrict__ w2,
    uint2* __restrict__ oq, uint2* __restrict__ oo,
    uint2* __restrict__ o1, uint2* __restrict__ o2)
{
    int i = blockIdx.x * 256 + threadIdx.x;
    const float4* s; uint2* d; int j;
    if (i < NWQ4)                     { s = wq; d = oq; j = i; }
    else if (i < NWQ4 + NWO4)         { s = wo; d = oo; j = i - NWQ4; }
    else if (i < NWQ4 + NWO4 + NW14)  { s = w1; d = o1; j = i - NWQ4 - NWO4; }
    else                              { s = w2; d = o2; j = i - NWQ4 - NWO4 - NW14; }
    float4 v = s[j];
    uint2 o;
    o.x = h2u(__floats2half2_rn(v.x, v.y));
    o.y = h2u(__floats2half2_rn(v.z, v.w));
    d[j] = o;
}

// ---------------- LayerNorm: fp16 + fp32 outputs ----------------
__global__ void __launch_bounds__(256) layernorm_k(
    const float* __restrict__ x, const float* __restrict__ w,
    const float* __restrict__ b, __half* __restrict__ yh, float* __restrict__ yf)
{
    int row = blockIdx.x;
    int tid = threadIdx.x;
    const float4* xr = (const float4*)(x + (size_t)row * CD);
    float4 xv = xr[tid];
    float s  = xv.x + xv.y + xv.z + xv.w;
    float ss = xv.x*xv.x + xv.y*xv.y + xv.z*xv.z + xv.w*xv.w;
    #pragma unroll
    for (int o = 16; o; o >>= 1) {
        s  += __shfl_xor_sync(0xffffffffu, s,  o);
        ss += __shfl_xor_sync(0xffffffffu, ss, o);
    }
    __shared__ float sm1[8], sm2[8];
    if ((tid & 31) == 0) { sm1[tid >> 5] = s; sm2[tid >> 5] = ss; }
    __syncthreads();
    float ts = 0.f, tss = 0.f;
    #pragma unroll
    for (int i = 0; i < 8; i++) { ts += sm1[i]; tss += sm2[i]; }
    float mu   = ts * (1.0f / CD);
    float var  = tss * (1.0f / CD) - mu * mu;
    float rstd = rsqrtf(var + 1e-5f);
    float4 wv = ((const float4*)w)[tid];
    float4 bv = ((const float4*)b)[tid];
    float4 ov;
    ov.x = (xv.x - mu) * rstd * wv.x + bv.x;
    ov.y = (xv.y - mu) * rstd * wv.y + bv.y;
    ov.z = (xv.z - mu) * rstd * wv.z + bv.z;
    ov.w = (xv.w - mu) * rstd * wv.w + bv.w;
    ((float4*)(yf + (size_t)row * CD))[tid] = ov;
    uint2 oh;
    oh.x = h2u(__floats2half2_rn(ov.x, ov.y));
    oh.y = h2u(__floats2half2_rn(ov.z, ov.w));
    ((uint2*)(yh + (size_t)row * CD))[tid] = oh;
}

// ---------------- fp16 mma.sync NT GEMM, 2 CTAs/SM (R9, proven) ----------------
#define NST     3
#define ROWB    144u
#define ATILE_B 18432u
#define ST_BYTE (2u*ATILE_B)
#define GSMEM   (NST*ST_BYTE)          // 110592

template<int EPI>
__global__ void __launch_bounds__(256, 2) gemm_mma(
    const __half* __restrict__ A, const __half* __restrict__ B,
    const float* __restrict__ bias, const float* __restrict__ res,
    void* __restrict__ Cv, int M, int N, int K)
{
    extern __shared__ char smc[];
    const uint32_t smb = smem_u32(smc);
    const int tid  = threadIdx.x;
    const int wid  = tid >> 5;
    const int lane = tid & 31;
    const int g = lane >> 2, c = lane & 3;
    const int wy = wid & 3, wx = wid >> 2;
    const int m0 = blockIdx.y * 128;
    const int n0 = blockIdx.x * 128;
    const int nch = K >> 6;

    const int lr = tid >> 3, lj = tid & 7;
    const __half* asrc0 = A + (size_t)(m0 + lr) * K + lj * 8;
    const __half* bsrc0 = B + (size_t)(n0 + lr) * K + lj * 8;
    const uint32_t adst0 = (uint32_t)lr * ROWB + (uint32_t)lj * 16u;
    const uint32_t bdst0 = ATILE_B + adst0;
    const size_t rstep = (size_t)32 * K;

    #pragma unroll
    for (int p = 0; p < NST - 1; p++) {
        uint32_t sb = smb + p * ST_BYTE;
        #pragma unroll
        for (int i = 0; i < 4; i++) {
            asm volatile("cp.async.cg.shared.global [%0], [%1], 16;"
                :: "r"(sb + adst0 + i*4608u), "l"(asrc0 + i*rstep + p*64));
            asm volatile("cp.async.cg.shared.global [%0], [%1], 16;"
                :: "r"(sb + bdst0 + i*4608u), "l"(bsrc0 + i*rstep + p*64));
        }
        asm volatile("cp.async.commit_group;");
    }

    float acc[2][8][4] = {};
    const uint32_t lrow  = (uint32_t)(lane & 15);
    const uint32_t lhalf = (uint32_t)(lane >> 4);

    for (int ch = 0; ch < nch; ch++) {
        asm volatile("cp.async.wait_group %0;" :: "n"(NST - 2));
        __syncthreads();

        int ch2 = ch + NST - 1;
        if (ch2 < nch) {
            uint32_t sb = smb + (uint32_t)(ch2 % NST) * ST_BYTE;
            #pragma unroll
            for (int i = 0; i < 4; i++) {
                asm volatile("cp.async.cg.shared.global [%0], [%1], 16;"
                    :: "r"(sb + adst0 + i*4608u), "l"(asrc0 + i*rstep + ch2*64));
                asm volatile("cp.async.cg.shared.global [%0], [%1], 16;"
                    :: "r"(sb + bdst0 + i*4608u), "l"(bsrc0 + i*rstep + ch2*64));
            }
        }
        asm volatile("cp.async.commit_group;");

        const uint32_t stb   = smb + (uint32_t)(ch % NST) * ST_BYTE;
        const uint32_t abase = stb + (uint32_t)(wy * 32 + lrow) * ROWB + lhalf * 16u;
        const uint32_t bbase = stb + ATILE_B
                             + (uint32_t)(wx * 64 + lrow) * ROWB + lhalf * 16u;

        #pragma unroll
        for (int ks = 0; ks < 4; ks++) {
            uint32_t koff = (uint32_t)ks * 32u;
            uint32_t af[2][4], bf[8][2];
            #pragma unroll
            for (int mf = 0; mf < 2; mf++)
                ldsm_x4(af[mf], abase + (uint32_t)mf * (16u * ROWB) + koff);
            #pragma unroll
            for (int np = 0; np < 4; np++) {
                uint32_t q[4];
                ldsm_x4(q, bbase + (uint32_t)np * (16u * ROWB) + koff);
                bf[2*np][0]   = q[0]; bf[2*np][1]   = q[2];
                bf[2*np+1][0] = q[1]; bf[2*np+1][1] = q[3];
            }
            #pragma unroll
            for (int mf = 0; mf < 2; mf++)
                #pragma unroll
                for (int nf = 0; nf < 8; nf++)
                    mma_f16(acc[mf][nf], af[mf], bf[nf]);
        }
    }

    const int mbase = m0 + wy * 32;
    const int nbase = n0 + wx * 64;
    #pragma unroll
    for (int mf = 0; mf < 2; mf++) {
        int r0 = mbase + mf * 16 + g;
        #pragma unroll
        for (int nf = 0; nf < 8; nf++) {
            int col = nbase + nf * 8 + c * 2;
            float v0 = acc[mf][nf][0], v1 = acc[mf][nf][1];
            float v2 = acc[mf][nf][2], v3 = acc[mf][nf][3];
            if (EPI >= 1) {
                float b0 = bias[col], b1 = bias[col + 1];
                v0 += b0; v1 += b1; v2 += b0; v3 += b1;
            }
            if (EPI == 1) {
                float* C = (float*)Cv;
                float2 r01 = *(const float2*)(res + (size_t)r0 * N + col);
                float2 r23 = *(const float2*)(res + (size_t)(r0 + 8) * N + col);
                *(float2*)(C + (size_t)r0 * N + col)       = make_float2(v0 + r01.x, v1 + r01.y);
                *(float2*)(C + (size_t)(r0 + 8) * N + col) = make_float2(v2 + r23.x, v3 + r23.y);
            } else {
                if (EPI == 2) {
                    v0 = v0 * normcdff(v0);
                    v1 = v1 * normcdff(v1);
                    v2 = v2 * normcdff(v2);
                    v3 = v3 * normcdff(v3);
                }
                __half* C = (__half*)Cv;
                *(uint32_t*)(C + (size_t)r0 * N + col)       = h2u(__floats2half2_rn(v0, v1));
                *(uint32_t*)(C + (size_t)(r0 + 8) * N + col) = h2u(__floats2half2_rn(v2, v3));
            }
        }
    }
}

// ---------------- Flash attention: q-tile 128, 3-stage cp.async K/V ring,
// Q frags hoisted, P kept in registers (no smem round-trip) ----------------
// smem halves (stride 72/row = 144B):
//   Qs[128][72] @0, K0..K2[64][72], V0..V2[64][72], mask float[3][64]
#define FH_STR 72
#define FH_QS  0
#define FH_K0  (128*FH_STR)                 // 9216
#define FH_V0  (FH_K0 + 3*64*FH_STR)        // 23040
#define FH_END (FH_V0 + 3*64*FH_STR)        // 36864 halves = 73728 B
#define FSM_TOT (FH_END*2 + 768)            // 74496 B

__global__ void __launch_bounds__(256, 2) flashm_k(
    const __half* __restrict__ qkv, const int* __restrict__ ids,
    __half* __restrict__ o)
{
    extern __shared__ char smc[];
    __half* smh = (__half*)smc;
    float*  mk  = (float*)(smc + FH_END*2);     // [3][64]
    const uint32_t smb = smem_u32(smc);

    const int tid = threadIdx.x;
    const int wid = tid >> 5, lane = tid & 31;
    const int g = lane >> 2, c = lane & 3;
    const int qt = blockIdx.x, h = blockIdx.y, b = blockIdx.z;
    const int q0 = qt * 128;
    const size_t rstr = 3 * CD;

    // per-thread K/V copy coords (512 uint4 over 256 threads: rows lr, lr+32)
    const int lr = tid >> 3, lj = tid & 7;
    const uint32_t kvoff = (uint32_t)lr * 144u + (uint32_t)lj * 16u;
    const __half* kvsrc = qkv + ((size_t)(b*CN + lr)) * rstr + CD + h*64 + lj*8;

    // load Q tile (synchronous)
    for (int i = tid; i < 1024; i += 256) {
        int r = i >> 3, j = i & 7;
        *(uint4*)(smh + FH_QS + r * FH_STR + j * 8) =
            *(const uint4*)(qkv + (size_t)(b*CN + q0 + r) * rstr + h*64 + j*8);
    }

    // prologue: async fill stages 0,1 (kt=0,1) + masks
    #pragma unroll
    for (int p = 0; p < 2; p++) {
        const __half* src = kvsrc + (size_t)(p * 64) * rstr;
        const uint32_t kd = smb + (FH_K0 + p*4608)*2 + kvoff;
        const uint32_t vd = smb + (FH_V0 + p*4608)*2 + kvoff;
        #pragma unroll
        for (int i = 0; i < 2; i++) {
            asm volatile("cp.async.cg.shared.global [%0], [%1], 16;"
                :: "r"(kd + i*4608u), "l"(src + (size_t)i*32*rstr));
            asm volatile("cp.async.cg.shared.global [%0], [%1], 16;"
                :: "r"(vd + i*4608u), "l"(src + (size_t)i*32*rstr + CD));
        }
        asm volatile("cp.async.commit_group;");
        if (tid < 64) mk[p*64 + tid] = -1.25e8f * (float)ids[b*CN + p*64 + tid];
    }
    __syncthreads();   // Q smem visible for fragment hoist

    // hoist Q fragments (loop-invariant)
    const uint32_t lrow  = (uint32_t)(lane & 15);
    const uint32_t lhalf = (uint32_t)(lane >> 4);
    uint32_t qf[4][4];
    {
        const uint32_t qbase = smb + (uint32_t)(wid*16 + lrow) * 144u + lhalf * 16u;
        #pragma unroll
        for (int ks = 0; ks < 4; ks++)
            ldsm_x4(qf[ks], qbase + (uint32_t)ks * 32u);
    }

    // per-stage ldmatrix base addresses (hoisted)
    uint32_t kb[3], vb[3];
    #pragma unroll
    for (int s = 0; s < 3; s++) {
        kb[s] = smb + (uint32_t)(FH_K0 + s*4608)*2 + lrow * 144u + lhalf * 16u;
        vb[s] = smb + (uint32_t)(FH_V0 + s*4608)*2 + lrow * 144u + lhalf * 16u;
    }

    float oa[8][4] = {};
    float m0 = -1e30f, m1 = -1e30f, l0 = 0.f, l1 = 0.f;

    int st = 0;                       // stage index kt % 3
    for (int kt = 0; kt < 16; kt++) {
        asm volatile("cp.async.wait_group 1;");
        __syncthreads();   // stage st data + mask visible; stage (kt+2)%3 free

        // issue stage kt+2 fill
        if (kt < 14) {
            const int s2 = (st + 2 >= 3) ? st - 1 : st + 2;
            const int k2 = (kt + 2) * 64;
            const __half* src = kvsrc + (size_t)k2 * rstr;
            const uint32_t kd = kb[s2] - (lrow * 144u + lhalf * 16u) + kvoff;
            const uint32_t vd = vb[s2] - (lrow * 144u + lhalf * 16u) + kvoff;
            #pragma unroll
            for (int i = 0; i < 2; i++) {
                asm volatile("cp.async.cg.shared.global [%0], [%1], 16;"
                    :: "r"(kd + i*4608u), "l"(src + (size_t)i*32*rstr));
                asm volatile("cp.async.cg.shared.global [%0], [%1], 16;"
                    :: "r"(vd + i*4608u), "l"(src + (size_t)i*32*rstr + CD));
            }
            if (tid < 64) mk[s2*64 + tid] = -1.25e8f * (float)ids[b*CN + k2 + tid];
        }
        asm volatile("cp.async.commit_group;");

        const uint32_t kbase = kb[st];
        const uint32_t vbase = vb[st];
        const float* mkc = mk + st * 64;

        // ---- S = Q @ K^T ----
        float sa[8][4] = {};
        #pragma unroll
        for (int ks = 0; ks < 4; ks++) {
            #pragma unroll
            for (int np = 0; np < 4; np++) {
                uint32_t q[4];
                ldsm_x4(q, kbase + (uint32_t)np * (16u*144u) + (uint32_t)ks * 32u);
                uint32_t b0[2] = {q[0], q[2]}, b1[2] = {q[1], q[3]};
                mma_f16(sa[2*np],   qf[ks], b0);
                mma_f16(sa[2*np+1], qf[ks], b1);
            }
        }

        // ---- scale + mask + online softmax (p kept in sa) ----
        float rmax0 = -1e30f, rmax1 = -1e30f;
        #pragma unroll
        for (int nf = 0; nf < 8; nf++) {
            float mv0 = mkc[nf*8 + 2*c], mv1 = mkc[nf*8 + 2*c + 1];
            sa[nf][0] = sa[nf][0]*0.125f + mv0; sa[nf][1] = sa[nf][1]*0.125f + mv1;
            sa[nf][2] = sa[nf][2]*0.125f + mv0; sa[nf][3] = sa[nf][3]*0.125f + mv1;
            rmax0 = fmaxf(rmax0, fmaxf(sa[nf][0], sa[nf][1]));
            rmax1 = fmaxf(rmax1, fmaxf(sa[nf][2], sa[nf][3]));
        }
        rmax0 = fmaxf(rmax0, __shfl_xor_sync(0xffffffffu, rmax0, 1));
        rmax0 = fmaxf(rmax0, __shfl_xor_sync(0xffffffffu, rmax0, 2));
        rmax1 = fmaxf(rmax1, __shfl_xor_sync(0xffffffffu, rmax1, 1));
        rmax1 = fmaxf(rmax1, __shfl_xor_sync(0xffffffffu, rmax1, 2));
        float mn0 = fmaxf(m0, rmax0), mn1 = fmaxf(m1, rmax1);
        float al0 = __expf(m0 - mn0), al1 = __expf(m1 - mn1);
        m0 = mn0; m1 = mn1;
        float ps0 = 0.f, ps1 = 0.f;
        #pragma unroll
        for (int nf = 0; nf < 8; nf++) {
            float p0 = __expf(sa[nf][0] - mn0);
            float p1 = __expf(sa[nf][1] - mn0);
            float p2 = __expf(sa[nf][2] - mn1);
            float p3 = __expf(sa[nf][3] - mn1);
            ps0 += p0 + p1; ps1 += p2 + p3;
            sa[nf][0] = p0; sa[nf][1] = p1; sa[nf][2] = p2; sa[nf][3] = p3;
        }
        ps0 += __shfl_xor_sync(0xffffffffu, ps0, 1);
        ps0 += __shfl_xor_sync(0xffffffffu, ps0, 2);
        ps1 += __shfl_xor_sync(0xffffffffu, ps1, 1);
        ps1 += __shfl_xor_sync(0xffffffffu, ps1, 2);
        l0 = l0 * al0 + ps0;
        l1 = l1 * al1 + ps1;
        #pragma unroll
        for (int nf = 0; nf < 8; nf++) {
            oa[nf][0] *= al0; oa[nf][1] *= al0;
            oa[nf][2] *= al1; oa[nf][3] *= al1;
        }

        // ---- O += P @ V (P A-fragments built directly from sa registers) ----
        #pragma unroll
        for (int ks = 0; ks < 4; ks++) {
            uint32_t a[4];
            a[0] = h2u(__floats2half2_rn(sa[2*ks][0],   sa[2*ks][1]));
            a[1] = h2u(__floats2half2_rn(sa[2*ks][2],   sa[2*ks][3]));
            a[2] = h2u(__floats2half2_rn(sa[2*ks+1][0], sa[2*ks+1][1]));
            a[3] = h2u(__floats2half2_rn(sa[2*ks+1][2], sa[2*ks+1][3]));
            #pragma unroll
            for (int np = 0; np < 4; np++) {
                uint32_t q[4];
                ldsm_x4_t(q, vbase + (uint32_t)ks * (16u*144u) + (uint32_t)np * 32u);
                uint32_t b0[2] = {q[0], q[1]}, b1[2] = {q[2], q[3]};
                mma_f16(oa[2*np],   a, b0);
                mma_f16(oa[2*np+1], a, b1);
            }
        }

        st = (st + 1 >= 3) ? 0 : st + 1;
    }

    // ---- epilogue ----
    float inv0 = 1.0f / l0, inv1 = 1.0f / l1;
    size_t r0 = (size_t)(b*CN + q0 + wid*16 + g) * CD + h*64;
    size_t r1 = (size_t)(b*CN + q0 + wid*16 + g + 8) * CD + h*64;
    #pragma unroll
    for (int nf = 0; nf < 8; nf++) {
        int col = nf*8 + 2*c;
        *(uint32_t*)(o + r0 + col) = h2u(__floats2half2_rn(oa[nf][0]*inv0, oa[nf][1]*inv0));
        *(uint32_t*)(o + r1 + col) = h2u(__floats2half2_rn(oa[nf][2]*inv1, oa[nf][3]*inv1));
    }
}

// ---------------- launch ----------------
extern "C" void kernel_launch(void* const* d_in, const int* in_sizes, int n_in,
                              void* d_out, int out_size)
{
    const float* x      = (const float*)d_in[0];
    const int*   ids    = (const int*)  d_in[1];
    const float* n1w    = (const float*)d_in[2];
    const float* n1b    = (const float*)d_in[3];
    const float* pin_w  = (const float*)d_in[4];
    const float* pout_w = (const float*)d_in[5];
    const float* pout_b = (const float*)d_in[6];
    const float* n2w    = (const float*)d_in[7];
    const float* n2b    = (const float*)d_in[8];
    const float* l1w    = (const float*)d_in[9];
    const float* l1b    = (const float*)d_in[10];
    const float* l2w    = (const float*)d_in[11];
    const float* l2b    = (const float*)d_in[12];
    float* out = (float*)d_out;

    __half *xnh, *qkvh, *aoh, *x2h, *hhh, *wqh, *woh, *w1h, *w2h;
    float *xnf, *x1f, *x2f;
    cudaGetSymbolAddress((void**)&xnh,  g_xn_h);
    cudaGetSymbolAddress((void**)&xnf,  g_xn_f);
    cudaGetSymbolAddress((void**)&qkvh, g_qkv_h);
    cudaGetSymbolAddress((void**)&aoh,  g_ao_h);
    cudaGetSymbolAddress((void**)&x1f,  g_x1_f);
    cudaGetSymbolAddress((void**)&x2h,  g_x2_h);
    cudaGetSymbolAddress((void**)&x2f,  g_x2_f);
    cudaGetSymbolAddress((void**)&hhh,  g_h_h);
    cudaGetSymbolAddress((void**)&wqh,  g_wq_h);
    cudaGetSymbolAddress((void**)&woh,  g_wo_h);
    cudaGetSymbolAddress((void**)&w1h,  g_w1_h);
    cudaGetSymbolAddress((void**)&w2h,  g_w2_h);

    cudaFuncSetAttribute(flashm_k,    cudaFuncAttributeMaxDynamicSharedMemorySize, FSM_TOT);
    cudaFuncSetAttribute(gemm_mma<0>, cudaFuncAttributeMaxDynamicSharedMemorySize, GSMEM);
    cudaFuncSetAttribute(gemm_mma<1>, cudaFuncAttributeMaxDynamicSharedMemorySize, GSMEM);
    cudaFuncSetAttribute(gemm_mma<2>, cudaFuncAttributeMaxDynamicSharedMemorySize, GSMEM);

    // 0) weights -> fp16 (single fused launch)
    round_all_k<<<NALL4/256, 256>>>(
        (const float4*)pin_w, (const float4*)pout_w, (const float4*)l1w, (const float4*)l2w,
        (uint2*)wqh, (uint2*)woh, (uint2*)w1h, (uint2*)w2h);

    // 1) xn = LN1(x)
    layernorm_k<<<NTOK, 256>>>(x, n1w, n1b, xnh, xnf);
    // 2) qkv = xn @ Wq^T  (fp16 out)
    gemm_mma<0><<<dim3(3*CD/128, NTOK/128), 256, GSMEM>>>(xnh, wqh, nullptr, nullptr, qkvh, NTOK, 3*CD, CD);
    // 3) flash attention -> ao (fp16)
    flashm_k<<<dim3(CN/128, CH, CB), 256, FSM_TOT>>>(qkvh, ids, aoh);
    // 4) x1 = ao @ Wo^T + bout + xn  (fp32 out)
    gemm_mma<1><<<dim3(CD/128, NTOK/128), 256, GSMEM>>>(aoh, woh, pout_b, xnf, x1f, NTOK, CD, CD);
    // 5) x2 = LN2(x1)
    layernorm_k<<<NTOK, 256>>>(x1f, n2w, n2b, x2h, x2f);
    // 6) h = gelu(x2 @ W1^T + b1)  (fp16 out)
    gemm_mma<2><<<dim3(CFF/128, NTOK/128), 256, GSMEM>>>(x2h, w1h, l1b, nullptr, hhh, NTOK, CFF, CD);
    // 7) out = h @ W2^T + b2 + x2  (fp32 out)
    gemm_mma<1><<<dim3(CD/128, NTOK/128), 256, GSMEM>>>(hhh, w2h, l2b, x2f, out, NTOK, CD, CFF);
}

// round 14
// speedup vs baseline: 1.0836x; 1.0037x over previous
#include <cuda_runtime.h>
#include <cuda_fp16.h>
#include <math.h>
#include <stdint.h>

#define CD   1024
#define CH   16
#define CFF  4096
#define CB   8
#define CN   1024
#define NTOK (CB*CN)   // 8192

// ---------------- scratch (no allocations allowed) ----------------
__device__ __half g_xn_h [NTOK*CD];
__device__ float  g_xn_f [NTOK*CD];
__device__ __half g_qkv_h[NTOK*3*CD];
__device__ __half g_ao_h [NTOK*CD];
__device__ float  g_x1_f [NTOK*CD];
__device__ __half g_x2_h [NTOK*CD];
__device__ float  g_x2_f [NTOK*CD];
__device__ __half g_h_h  [NTOK*CFF];
__device__ __half g_wq_h [3*CD*CD];
__device__ __half g_wo_h [CD*CD];
__device__ __half g_w1_h [CFF*CD];
__device__ __half g_w2_h [CD*CFF];

// ---------------- helpers ----------------
__device__ __forceinline__ uint32_t smem_u32(const void* p) {
    uint32_t a;
    asm("{ .reg .u64 t; cvta.to.shared.u64 t, %1; cvt.u32.u64 %0, t; }" : "=r"(a) : "l"(p));
    return a;
}
__device__ __forceinline__ void mma_f16(float* d, const uint32_t* a, const uint32_t* b) {
    asm volatile(
        "mma.sync.aligned.m16n8k16.row.col.f32.f16.f16.f32 "
        "{%0,%1,%2,%3},{%4,%5,%6,%7},{%8,%9},{%0,%1,%2,%3};"
        : "+f"(d[0]), "+f"(d[1]), "+f"(d[2]), "+f"(d[3])
        : "r"(a[0]), "r"(a[1]), "r"(a[2]), "r"(a[3]), "r"(b[0]), "r"(b[1]));
}
__device__ __forceinline__ void ldsm_x4(uint32_t* r, uint32_t addr) {
    asm volatile("ldmatrix.sync.aligned.m8n8.x4.shared.b16 {%0,%1,%2,%3}, [%4];"
        : "=r"(r[0]), "=r"(r[1]), "=r"(r[2]), "=r"(r[3]) : "r"(addr));
}
__device__ __forceinline__ void ldsm_x4_t(uint32_t* r, uint32_t addr) {
    asm volatile("ldmatrix.sync.aligned.m8n8.x4.trans.shared.b16 {%0,%1,%2,%3}, [%4];"
        : "=r"(r[0]), "=r"(r[1]), "=r"(r[2]), "=r"(r[3]) : "r"(addr));
}
__device__ __forceinline__ uint32_t h2u(__half2 h) { return *(uint32_t*)&h; }

// ---------------- fused fp16 rounding, 4 elems/thread (MLP=4) ----------
#define NWQ4 (3*CD*CD/4)
#define NWO4 (CD*CD/4)
#define NW14 (CFF*CD/4)
#define NW24 (CD*CFF/4)
#define NALL4 (NWQ4 + NWO4 + NW14 + NW24)   // 3145728

__global__ void __launch_bounds__(256) round_all_k(
    const float4* __restrict__ wq, const float4* __restrict__ wo,
    const float4* __restrict__ w1, const float4* __restrict__ w2,
    uint2* __restrict__ oq, uint2* __restrict__ oo,
    uint2* __restrict__ o1, uint2* __restrict__ o2)
{
    int base = blockIdx.x * 1024 + threadIdx.x;
    float4 v[4];
    const float4* s[4]; uint2* d[4]; int j[4];
    #pragma unroll
    for (int k = 0; k < 4; k++) {
        int i = base + k * 256;
        if (i < NWQ4)                     { s[k] = wq; d[k] = oq; j[k] = i; }
        else if (i < NWQ4 + NWO4)         { s[k] = wo; d[k] = oo; j[k] = i - NWQ4; }
        else if (i < NWQ4 + NWO4 + NW14)  { s[k] = w1; d[k] = o1; j[k] = i - NWQ4 - NWO4; }
        else                              { s[k] = w2; d[k] = o2; j[k] = i - NWQ4 - NWO4 - NW14; }
        v[k] = s[k][j[k]];
    }
    #pragma unroll
    for (int k = 0; k < 4; k++) {
        uint2 o;
        o.x = h2u(__floats2half2_rn(v[k].x, v[k].y));
        o.y = h2u(__floats2half2_rn(v[k].z, v[k].w));
        d[k][j[k]] = o;
    }
}

// ---------------- LayerNorm: fp16 + fp32 outputs ----------------
__global__ void __launch_bounds__(256) layernorm_k(
    const float* __restrict__ x, const float* __restrict__ w,
    const float* __restrict__ b, __half* __restrict__ yh, float* __restrict__ yf)
{
    int row = blockIdx.x;
    int tid = threadIdx.x;
    const float4* xr = (const float4*)(x + (size_t)row * CD);
    float4 xv = xr[tid];
    float s  = xv.x + xv.y + xv.z + xv.w;
    float ss = xv.x*xv.x + xv.y*xv.y + xv.z*xv.z + xv.w*xv.w;
    #pragma unroll
    for (int o = 16; o; o >>= 1) {
        s  += __shfl_xor_sync(0xffffffffu, s,  o);
        ss += __shfl_xor_sync(0xffffffffu, ss, o);
    }
    __shared__ float sm1[8], sm2[8];
    if ((tid & 31) == 0) { sm1[tid >> 5] = s; sm2[tid >> 5] = ss; }
    __syncthreads();
    float ts = 0.f, tss = 0.f;
    #pragma unroll
    for (int i = 0; i < 8; i++) { ts += sm1[i]; tss += sm2[i]; }
    float mu   = ts * (1.0f / CD);
    float var  = tss * (1.0f / CD) - mu * mu;
    float rstd = rsqrtf(var + 1e-5f);
    float4 wv = ((const float4*)w)[tid];
    float4 bv = ((const float4*)b)[tid];
    float4 ov;
    ov.x = (xv.x - mu) * rstd * wv.x + bv.x;
    ov.y = (xv.y - mu) * rstd * wv.y + bv.y;
    ov.z = (xv.z - mu) * rstd * wv.z + bv.z;
    ov.w = (xv.w - mu) * rstd * wv.w + bv.w;
    ((float4*)(yf + (size_t)row * CD))[tid] = ov;
    uint2 oh;
    oh.x = h2u(__floats2half2_rn(ov.x, ov.y));
    oh.y = h2u(__floats2half2_rn(ov.z, ov.w));
    ((uint2*)(yh + (size_t)row * CD))[tid] = oh;
}

// ---------------- fp16 mma.sync NT GEMM, 2 CTAs/SM (R9, proven) ----------------
#define NST     3
#define ROWB    144u
#define ATILE_B 18432u
#define ST_BYTE (2u*ATILE_B)
#define GSMEM   (NST*ST_BYTE)          // 110592

template<int EPI>
__global__ void __launch_bounds__(256, 2) gemm_mma(
    const __half* __restrict__ A, const __half* __restrict__ B,
    const float* __restrict__ bias, const float* __restrict__ res,
    void* __restrict__ Cv, int M, int N, int K)
{
    extern __shared__ char smc[];
    const uint32_t smb = smem_u32(smc);
    const int tid  = threadIdx.x;
    const int wid  = tid >> 5;
    const int lane = tid & 31;
    const int g = lane >> 2, c = lane & 3;
    const int wy = wid & 3, wx = wid >> 2;
    const int m0 = blockIdx.y * 128;
    const int n0 = blockIdx.x * 128;
    const int nch = K >> 6;

    const int lr = tid >> 3, lj = tid & 7;
    const __half* asrc0 = A + (size_t)(m0 + lr) * K + lj * 8;
    const __half* bsrc0 = B + (size_t)(n0 + lr) * K + lj * 8;
    const uint32_t adst0 = (uint32_t)lr * ROWB + (uint32_t)lj * 16u;
    const uint32_t bdst0 = ATILE_B + adst0;
    const size_t rstep = (size_t)32 * K;

    #pragma unroll
    for (int p = 0; p < NST - 1; p++) {
        uint32_t sb = smb + p * ST_BYTE;
        #pragma unroll
        for (int i = 0; i < 4; i++) {
            asm volatile("cp.async.cg.shared.global [%0], [%1], 16;"
                :: "r"(sb + adst0 + i*4608u), "l"(asrc0 + i*rstep + p*64));
            asm volatile("cp.async.cg.shared.global [%0], [%1], 16;"
                :: "r"(sb + bdst0 + i*4608u), "l"(bsrc0 + i*rstep + p*64));
        }
        asm volatile("cp.async.commit_group;");
    }

    float acc[2][8][4] = {};
    const uint32_t lrow  = (uint32_t)(lane & 15);
    const uint32_t lhalf = (uint32_t)(lane >> 4);

    for (int ch = 0; ch < nch; ch++) {
        asm volatile("cp.async.wait_group %0;" :: "n"(NST - 2));
        __syncthreads();

        int ch2 = ch + NST - 1;
        if (ch2 < nch) {
            uint32_t sb = smb + (uint32_t)(ch2 % NST) * ST_BYTE;
            #pragma unroll
            for (int i = 0; i < 4; i++) {
                asm volatile("cp.async.cg.shared.global [%0], [%1], 16;"
                    :: "r"(sb + adst0 + i*4608u), "l"(asrc0 + i*rstep + ch2*64));
                asm volatile("cp.async.cg.shared.global [%0], [%1], 16;"
                    :: "r"(sb + bdst0 + i*4608u), "l"(bsrc0 + i*rstep + ch2*64));
            }
        }
        asm volatile("cp.async.commit_group;");

        const uint32_t stb   = smb + (uint32_t)(ch % NST) * ST_BYTE;
        const uint32_t abase = stb + (uint32_t)(wy * 32 + lrow) * ROWB + lhalf * 16u;
        const uint32_t bbase = stb + ATILE_B
                             + (uint32_t)(wx * 64 + lrow) * ROWB + lhalf * 16u;

        #pragma unroll
        for (int ks = 0; ks < 4; ks++) {
            uint32_t koff = (uint32_t)ks * 32u;
            uint32_t af[2][4], bf[8][2];
            #pragma unroll
            for (int mf = 0; mf < 2; mf++)
                ldsm_x4(af[mf], abase + (uint32_t)mf * (16u * ROWB) + koff);
            #pragma unroll
            for (int np = 0; np < 4; np++) {
                uint32_t q[4];
                ldsm_x4(q, bbase + (uint32_t)np * (16u * ROWB) + koff);
                bf[2*np][0]   = q[0]; bf[2*np][1]   = q[2];
                bf[2*np+1][0] = q[1]; bf[2*np+1][1] = q[3];
            }
            #pragma unroll
            for (int mf = 0; mf < 2; mf++)
                #pragma unroll
                for (int nf = 0; nf < 8; nf++)
                    mma_f16(acc[mf][nf], af[mf], bf[nf]);
        }
    }

    const int mbase = m0 + wy * 32;
    const int nbase = n0 + wx * 64;
    #pragma unroll
    for (int mf = 0; mf < 2; mf++) {
        int r0 = mbase + mf * 16 + g;
        #pragma unroll
        for (int nf = 0; nf < 8; nf++) {
            int col = nbase + nf * 8 + c * 2;
            float v0 = acc[mf][nf][0], v1 = acc[mf][nf][1];
            float v2 = acc[mf][nf][2], v3 = acc[mf][nf][3];
            if (EPI >= 1) {
                float b0 = bias[col], b1 = bias[col + 1];
                v0 += b0; v1 += b1; v2 += b0; v3 += b1;
            }
            if (EPI == 1) {
                float* C = (float*)Cv;
                float2 r01 = *(const float2*)(res + (size_t)r0 * N + col);
                float2 r23 = *(const float2*)(res + (size_t)(r0 + 8) * N + col);
                *(float2*)(C + (size_t)r0 * N + col)       = make_float2(v0 + r01.x, v1 + r01.y);
                *(float2*)(C + (size_t)(r0 + 8) * N + col) = make_float2(v2 + r23.x, v3 + r23.y);
            } else {
                if (EPI == 2) {
                    v0 = v0 * normcdff(v0);
                    v1 = v1 * normcdff(v1);
                    v2 = v2 * normcdff(v2);
                    v3 = v3 * normcdff(v3);
                }
                __half* C = (__half*)Cv;
                *(uint32_t*)(C + (size_t)r0 * N + col)       = h2u(__floats2half2_rn(v0, v1));
                *(uint32_t*)(C + (size_t)(r0 + 8) * N + col) = h2u(__floats2half2_rn(v2, v3));
            }
        }
    }
}

// ---------------- Flash attention: q-tile 128, 3-stage cp.async K/V ring,
// Q frags + cp.async dsts hoisted, P in registers, exp2-domain softmax -------
#define FH_STR 72
#define FH_QS  0
#define FH_K0  (128*FH_STR)
#define FH_V0  (FH_K0 + 3*64*FH_STR)
#define FH_END (FH_V0 + 3*64*FH_STR)        // 36864 halves = 73728 B
#define FSM_TOT (FH_END*2 + 768)
#define FSC   0.18033688f                   // 0.125 * log2(e)
#define FMK  -1.803368801e8f                // -1e9 * 0.125 * log2(e)

__global__ void __launch_bounds__(256, 2) flashm_k(
    const __half* __restrict__ qkv, const int* __restrict__ ids,
    __half* __restrict__ o)
{
    extern __shared__ char smc[];
    __half* smh = (__half*)smc;
    float*  mk  = (float*)(smc + FH_END*2);     // [3][64]
    const uint32_t smb = smem_u32(smc);

    const int tid = threadIdx.x;
    const int wid = tid >> 5, lane = tid & 31;
    const int g = lane >> 2, c = lane & 3;
    const int qt = blockIdx.x, h = blockIdx.y, b = blockIdx.z;
    const int q0 = qt * 128;
    const size_t rstr = 3 * CD;

    const int lr = tid >> 3, lj = tid & 7;
    const uint32_t kvoff = (uint32_t)lr * 144u + (uint32_t)lj * 16u;
    const __half* kvsrc = qkv + ((size_t)(b*CN + lr)) * rstr + CD + h*64 + lj*8;

    // load Q tile
    for (int i = tid; i < 1024; i += 256) {
        int r = i >> 3, j = i & 7;
        *(uint4*)(smh + FH_QS + r * FH_STR + j * 8) =
            *(const uint4*)(qkv + (size_t)(b*CN + q0 + r) * rstr + h*64 + j*8);
    }

    // prologue: async fill stages 0,1 + masks
    #pragma unroll
    for (int p = 0; p < 2; p++) {
        const __half* src = kvsrc + (size_t)(p * 64) * rstr;
        const uint32_t kd = smb + (FH_K0 + p*4608)*2 + kvoff;
        const uint32_t vd = smb + (FH_V0 + p*4608)*2 + kvoff;
        #pragma unroll
        for (int i = 0; i < 2; i++) {
            asm volatile("cp.async.cg.shared.global [%0], [%1], 16;"
                :: "r"(kd + i*4608u), "l"(src + (size_t)i*32*rstr));
            asm volatile("cp.async.cg.shared.global [%0], [%1], 16;"
                :: "r"(vd + i*4608u), "l"(src + (size_t)i*32*rstr + CD));
        }
        asm volatile("cp.async.commit_group;");
        if (tid < 64) mk[p*64 + tid] = FMK * (float)ids[b*CN + p*64 + tid];
    }
    __syncthreads();

    // hoist Q fragments
    const uint32_t lrow  = (uint32_t)(lane & 15);
    const uint32_t lhalf = (uint32_t)(lane >> 4);
    uint32_t qf[4][4];
    {
        const uint32_t qbase = smb + (uint32_t)(wid*16 + lrow) * 144u + lhalf * 16u;
        #pragma unroll
        for (int ks = 0; ks < 4; ks++)
            ldsm_x4(qf[ks], qbase + (uint32_t)ks * 32u);
    }

    // hoisted per-stage ldmatrix bases AND cp.async destinations
    uint32_t kb[3], vb[3], kd[3], vd[3];
    #pragma unroll
    for (int s = 0; s < 3; s++) {
        kb[s] = smb + (uint32_t)(FH_K0 + s*4608)*2 + lrow * 144u + lhalf * 16u;
        vb[s] = smb + (uint32_t)(FH_V0 + s*4608)*2 + lrow * 144u + lhalf * 16u;
        kd[s] = smb + (uint32_t)(FH_K0 + s*4608)*2 + kvoff;
        vd[s] = smb + (uint32_t)(FH_V0 + s*4608)*2 + kvoff;
    }

    float oa[8][4] = {};
    float m0 = -1e30f, m1 = -1e30f, l0 = 0.f, l1 = 0.f;

    int st = 0;
    for (int kt = 0; kt < 16; kt++) {
        asm volatile("cp.async.wait_group 1;");
        __syncthreads();

        if (kt < 14) {
            const int s2 = (st + 2 >= 3) ? st - 1 : st + 2;
            const int k2 = (kt + 2) * 64;
            const __half* src = kvsrc + (size_t)k2 * rstr;
            #pragma unroll
            for (int i = 0; i < 2; i++) {
                asm volatile("cp.async.cg.shared.global [%0], [%1], 16;"
                    :: "r"(kd[s2] + i*4608u), "l"(src + (size_t)i*32*rstr));
                asm volatile("cp.async.cg.shared.global [%0], [%1], 16;"
                    :: "r"(vd[s2] + i*4608u), "l"(src + (size_t)i*32*rstr + CD));
            }
            if (tid < 64) mk[s2*64 + tid] = FMK * (float)ids[b*CN + k2 + tid];
        }
        asm volatile("cp.async.commit_group;");

        const uint32_t kbase = kb[st];
        const uint32_t vbase = vb[st];
        const float* mkc = mk + st * 64;

        // ---- S = Q @ K^T ----
        float sa[8][4] = {};
        #pragma unroll
        for (int ks = 0; ks < 4; ks++) {
            #pragma unroll
            for (int np = 0; np < 4; np++) {
                uint32_t q[4];
                ldsm_x4(q, kbase + (uint32_t)np * (16u*144u) + (uint32_t)ks * 32u);
                uint32_t b0[2] = {q[0], q[2]}, b1[2] = {q[1], q[3]};
                mma_f16(sa[2*np],   qf[ks], b0);
                mma_f16(sa[2*np+1], qf[ks], b1);
            }
        }

        // ---- scale+mask (log2 domain) + online softmax via exp2 ----
        float rmax0 = -1e30f, rmax1 = -1e30f;
        #pragma unroll
        for (int nf = 0; nf < 8; nf++) {
            float mv0 = mkc[nf*8 + 2*c], mv1 = mkc[nf*8 + 2*c + 1];
            sa[nf][0] = fmaf(sa[nf][0], FSC, mv0); sa[nf][1] = fmaf(sa[nf][1], FSC, mv1);
            sa[nf][2] = fmaf(sa[nf][2], FSC, mv0); sa[nf][3] = fmaf(sa[nf][3], FSC, mv1);
            rmax0 = fmaxf(rmax0, fmaxf(sa[nf][0], sa[nf][1]));
            rmax1 = fmaxf(rmax1, fmaxf(sa[nf][2], sa[nf][3]));
        }
        rmax0 = fmaxf(rmax0, __shfl_xor_sync(0xffffffffu, rmax0, 1));
        rmax0 = fmaxf(rmax0, __shfl_xor_sync(0xffffffffu, rmax0, 2));
        rmax1 = fmaxf(rmax1, __shfl_xor_sync(0xffffffffu, rmax1, 1));
        rmax1 = fmaxf(rmax1, __shfl_xor_sync(0xffffffffu, rmax1, 2));
        float mn0 = fmaxf(m0, rmax0), mn1 = fmaxf(m1, rmax1);
        float al0 = exp2f(m0 - mn0), al1 = exp2f(m1 - mn1);
        m0 = mn0; m1 = mn1;
        float ps0 = 0.f, ps1 = 0.f;
        #pragma unroll
        for (int nf = 0; nf < 8; nf++) {
            float p0 = exp2f(sa[nf][0] - mn0);
            float p1 = exp2f(sa[nf][1] - mn0);
            float p2 = exp2f(sa[nf][2] - mn1);
            float p3 = exp2f(sa[nf][3] - mn1);
            ps0 += p0 + p1; ps1 += p2 + p3;
            sa[nf][0] = p0; sa[nf][1] = p1; sa[nf][2] = p2; sa[nf][3] = p3;
        }
        ps0 += __shfl_xor_sync(0xffffffffu, ps0, 1);
        ps0 += __shfl_xor_sync(0xffffffffu, ps0, 2);
        ps1 += __shfl_xor_sync(0xffffffffu, ps1, 1);
        ps1 += __shfl_xor_sync(0xffffffffu, ps1, 2);
        l0 = l0 * al0 + ps0;
        l1 = l1 * al1 + ps1;
        #pragma unroll
        for (int nf = 0; nf < 8; nf++) {
            oa[nf][0] *= al0; oa[nf][1] *= al0;
            oa[nf][2] *= al1; oa[nf][3] *= al1;
        }

        // ---- O += P @ V (P A-fragments straight from registers) ----
        #pragma unroll
        for (int ks = 0; ks < 4; ks++) {
            uint32_t a[4];
            a[0] = h2u(__floats2half2_rn(sa[2*ks][0],   sa[2*ks][1]));
            a[1] = h2u(__floats2half2_rn(sa[2*ks][2],   sa[2*ks][3]));
            a[2] = h2u(__floats2half2_rn(sa[2*ks+1][0], sa[2*ks+1][1]));
            a[3] = h2u(__floats2half2_rn(sa[2*ks+1][2], sa[2*ks+1][3]));
            #pragma unroll
            for (int np = 0; np < 4; np++) {
                uint32_t q[4];
                ldsm_x4_t(q, vbase + (uint32_t)ks * (16u*144u) + (uint32_t)np * 32u);
                uint32_t b0[2] = {q[0], q[1]}, b1[2] = {q[2], q[3]};
                mma_f16(oa[2*np],   a, b0);
                mma_f16(oa[2*np+1], a, b1);
            }
        }

        st = (st + 1 >= 3) ? 0 : st + 1;
    }

    // ---- epilogue ----
    float inv0 = 1.0f / l0, inv1 = 1.0f / l1;
    size_t r0 = (size_t)(b*CN + q0 + wid*16 + g) * CD + h*64;
    size_t r1 = (size_t)(b*CN + q0 + wid*16 + g + 8) * CD + h*64;
    #pragma unroll
    for (int nf = 0; nf < 8; nf++) {
        int col = nf*8 + 2*c;
        *(uint32_t*)(o + r0 + col) = h2u(__floats2half2_rn(oa[nf][0]*inv0, oa[nf][1]*inv0));
        *(uint32_t*)(o + r1 + col) = h2u(__floats2half2_rn(oa[nf][2]*inv1, oa[nf][3]*inv1));
    }
}

// ---------------- launch ----------------
extern "C" void kernel_launch(void* const* d_in, const int* in_sizes, int n_in,
                              void* d_out, int out_size)
{
    const float* x      = (const float*)d_in[0];
    const int*   ids    = (const int*)  d_in[1];
    const float* n1w    = (const float*)d_in[2];
    const float* n1b    = (const float*)d_in[3];
    const float* pin_w  = (const float*)d_in[4];
    const float* pout_w = (const float*)d_in[5];
    const float* pout_b = (const float*)d_in[6];
    const float* n2w    = (const float*)d_in[7];
    const float* n2b    = (const float*)d_in[8];
    const float* l1w    = (const float*)d_in[9];
    const float* l1b    = (const float*)d_in[10];
    const float* l2w    = (const float*)d_in[11];
    const float* l2b    = (const float*)d_in[12];
    float* out = (float*)d_out;

    __half *xnh, *qkvh, *aoh, *x2h, *hhh, *wqh, *woh, *w1h, *w2h;
    float *xnf, *x1f, *x2f;
    cudaGetSymbolAddress((void**)&xnh,  g_xn_h);
    cudaGetSymbolAddress((void**)&xnf,  g_xn_f);
    cudaGetSymbolAddress((void**)&qkvh, g_qkv_h);
    cudaGetSymbolAddress((void**)&aoh,  g_ao_h);
    cudaGetSymbolAddress((void**)&x1f,  g_x1_f);
    cudaGetSymbolAddress((void**)&x2h,  g_x2_h);
    cudaGetSymbolAddress((void**)&x2f,  g_x2_f);
    cudaGetSymbolAddress((void**)&hhh,  g_h_h);
    cudaGetSymbolAddress((void**)&wqh,  g_wq_h);
    cudaGetSymbolAddress((void**)&woh,  g_wo_h);
    cudaGetSymbolAddress((void**)&w1h,  g_w1_h);
    cudaGetSymbolAddress((void**)&w2h,  g_w2_h);

    cudaFuncSetAttribute(flashm_k,    cudaFuncAttributeMaxDynamicSharedMemorySize, FSM_TOT);
    cudaFuncSetAttribute(gemm_mma<0>, cudaFuncAttributeMaxDynamicSharedMemorySize, GSMEM);
    cudaFuncSetAttribute(gemm_mma<1>, cudaFuncAttributeMaxDynamicSharedMemorySize, GSMEM);
    cudaFuncSetAttribute(gemm_mma<2>, cudaFuncAttributeMaxDynamicSharedMemorySize, GSMEM);

    // 0) weights -> fp16 (single fused launch, 4 elems/thread)
    round_all_k<<<NALL4/1024, 256>>>(
        (const float4*)pin_w, (const float4*)pout_w, (const float4*)l1w, (const float4*)l2w,
        (uint2*)wqh, (uint2*)woh, (uint2*)w1h, (uint2*)w2h);

    // 1) xn = LN1(x)
    layernorm_k<<<NTOK, 256>>>(x, n1w, n1b, xnh, xnf);
    // 2) qkv = xn @ Wq^T  (fp16 out)
    gemm_mma<0><<<dim3(3*CD/128, NTOK/128), 256, GSMEM>>>(xnh, wqh, nullptr, nullptr, qkvh, NTOK, 3*CD, CD);
    // 3) flash attention -> ao (fp16)
    flashm_k<<<dim3(CN/128, CH, CB), 256, FSM_TOT>>>(qkvh, ids, aoh);
    // 4) x1 = ao @ Wo^T + bout + xn  (fp32 out)
    gemm_mma<1><<<dim3(CD/128, NTOK/128), 256, GSMEM>>>(aoh, woh, pout_b, xnf, x1f, NTOK, CD, CD);
    // 5) x2 = LN2(x1)
    layernorm_k<<<NTOK, 256>>>(x1f, n2w, n2b, x2h, x2f);
    // 6) h = gelu(x2 @ W1^T + b1)  (fp16 out)
    gemm_mma<2><<<dim3(CFF/128, NTOK/128), 256, GSMEM>>>(x2h, w1h, l1b, nullptr, hhh, NTOK, CFF, CD);
    // 7) out = h @ W2^T + b2 + x2  (fp32 out)
    gemm_mma<1><<<dim3(CD/128, NTOK/128), 256, GSMEM>>>(hhh, w2h, l2b, x2f, out, NTOK, CD, CFF);
}

// round 15
// speedup vs baseline: 1.0860x; 1.0022x over previous
#include <cuda_runtime.h>
#include <cuda_fp16.h>
#include <math.h>
#include <stdint.h>

#define CD   1024
#define CH   16
#define CFF  4096
#define CB   8
#define CN   1024
#define NTOK (CB*CN)   // 8192

// ---------------- scratch (no allocations allowed) ----------------
__device__ __half g_xn_h [NTOK*CD];
__device__ float  g_xn_f [NTOK*CD];
__device__ __half g_qkv_h[NTOK*3*CD];
__device__ __half g_ao_h [NTOK*CD];
__device__ float  g_x1_f [NTOK*CD];
__device__ __half g_x2_h [NTOK*CD];
__device__ float  g_x2_f [NTOK*CD];
__device__ __half g_h_h  [NTOK*CFF];
__device__ __half g_wq_h [3*CD*CD];
__device__ __half g_wo_h [CD*CD];
__device__ __half g_w1_h [CFF*CD];
__device__ __half g_w2_h [CD*CFF];

// ---------------- helpers ----------------
__device__ __forceinline__ uint32_t smem_u32(const void* p) {
    uint32_t a;
    asm("{ .reg .u64 t; cvta.to.shared.u64 t, %1; cvt.u32.u64 %0, t; }" : "=r"(a) : "l"(p));
    return a;
}
__device__ __forceinline__ void mma_f16(float* d, const uint32_t* a, const uint32_t* b) {
    asm volatile(
        "mma.sync.aligned.m16n8k16.row.col.f32.f16.f16.f32 "
        "{%0,%1,%2,%3},{%4,%5,%6,%7},{%8,%9},{%0,%1,%2,%3};"
        : "+f"(d[0]), "+f"(d[1]), "+f"(d[2]), "+f"(d[3])
        : "r"(a[0]), "r"(a[1]), "r"(a[2]), "r"(a[3]), "r"(b[0]), "r"(b[1]));
}
__device__ __forceinline__ void ldsm_x4(uint32_t* r, uint32_t addr) {
    asm volatile("ldmatrix.sync.aligned.m8n8.x4.shared.b16 {%0,%1,%2,%3}, [%4];"
        : "=r"(r[0]), "=r"(r[1]), "=r"(r[2]), "=r"(r[3]) : "r"(addr));
}
__device__ __forceinline__ void ldsm_x4_t(uint32_t* r, uint32_t addr) {
    asm volatile("ldmatrix.sync.aligned.m8n8.x4.trans.shared.b16 {%0,%1,%2,%3}, [%4];"
        : "=r"(r[0]), "=r"(r[1]), "=r"(r[2]), "=r"(r[3]) : "r"(addr));
}
__device__ __forceinline__ uint32_t h2u(__half2 h) { return *(uint32_t*)&h; }

// ---------------- weight-rounding sizes ----------
#define NWQ4 (3*CD*CD/4)
#define NWO4 (CD*CD/4)
#define NW14 (CFF*CD/4)
#define NW24 (CD*CFF/4)
#define NALL4 (NWQ4 + NWO4 + NW14 + NW24)   // 3145728
#define NRBLK (NALL4/1024)                  // 3072 rounding blocks

// ---------------- LN row body (shared by fused + standalone kernels) ------
__device__ __forceinline__ void ln_row(
    int row, int tid,
    const float* __restrict__ x, const float* __restrict__ w,
    const float* __restrict__ b, __half* __restrict__ yh, float* __restrict__ yf,
    float* sm1, float* sm2)
{
    const float4* xr = (const float4*)(x + (size_t)row * CD);
    float4 xv = xr[tid];
    float s  = xv.x + xv.y + xv.z + xv.w;
    float ss = xv.x*xv.x + xv.y*xv.y + xv.z*xv.z + xv.w*xv.w;
    #pragma unroll
    for (int o = 16; o; o >>= 1) {
        s  += __shfl_xor_sync(0xffffffffu, s,  o);
        ss += __shfl_xor_sync(0xffffffffu, ss, o);
    }
    if ((tid & 31) == 0) { sm1[tid >> 5] = s; sm2[tid >> 5] = ss; }
    __syncthreads();
    float ts = 0.f, tss = 0.f;
    #pragma unroll
    for (int i = 0; i < 8; i++) { ts += sm1[i]; tss += sm2[i]; }
    float mu   = ts * (1.0f / CD);
    float var  = tss * (1.0f / CD) - mu * mu;
    float rstd = rsqrtf(var + 1e-5f);
    float4 wv = ((const float4*)w)[tid];
    float4 bv = ((const float4*)b)[tid];
    float4 ov;
    ov.x = (xv.x - mu) * rstd * wv.x + bv.x;
    ov.y = (xv.y - mu) * rstd * wv.y + bv.y;
    ov.z = (xv.z - mu) * rstd * wv.z + bv.z;
    ov.w = (xv.w - mu) * rstd * wv.w + bv.w;
    ((float4*)(yf + (size_t)row * CD))[tid] = ov;
    uint2 oh;
    oh.x = h2u(__floats2half2_rn(ov.x, ov.y));
    oh.y = h2u(__floats2half2_rn(ov.z, ov.w));
    ((uint2*)(yh + (size_t)row * CD))[tid] = oh;
}

// ---------------- fused: LN1 (blocks 0..NTOK-1) + weight rounding ----------
__global__ void __launch_bounds__(256) ln1_round_k(
    const float* __restrict__ x, const float* __restrict__ n1w,
    const float* __restrict__ n1b, __half* __restrict__ yh, float* __restrict__ yf,
    const float4* __restrict__ wq, const float4* __restrict__ wo,
    const float4* __restrict__ w1, const float4* __restrict__ w2,
    uint2* __restrict__ oq, uint2* __restrict__ oo,
    uint2* __restrict__ o1, uint2* __restrict__ o2)
{
    __shared__ float sm1[8], sm2[8];
    const int tid = threadIdx.x;
    if (blockIdx.x < NTOK) {
        ln_row(blockIdx.x, tid, x, n1w, n1b, yh, yf, sm1, sm2);
        return;
    }
    // weight rounding: 4 float4 per thread (MLP=4)
    int base = (blockIdx.x - NTOK) * 1024 + tid;
    float4 v[4];
    const float4* s[4]; uint2* d[4]; int j[4];
    #pragma unroll
    for (int k = 0; k < 4; k++) {
        int i = base + k * 256;
        if (i < NWQ4)                     { s[k] = wq; d[k] = oq; j[k] = i; }
        else if (i < NWQ4 + NWO4)         { s[k] = wo; d[k] = oo; j[k] = i - NWQ4; }
        else if (i < NWQ4 + NWO4 + NW14)  { s[k] = w1; d[k] = o1; j[k] = i - NWQ4 - NWO4; }
        else                              { s[k] = w2; d[k] = o2; j[k] = i - NWQ4 - NWO4 - NW14; }
        v[k] = s[k][j[k]];
    }
    #pragma unroll
    for (int k = 0; k < 4; k++) {
        uint2 o;
        o.x = h2u(__floats2half2_rn(v[k].x, v[k].y));
        o.y = h2u(__floats2half2_rn(v[k].z, v[k].w));
        d[k][j[k]] = o;
    }
}

// ---------------- standalone LayerNorm (LN2) ----------------
__global__ void __launch_bounds__(256) layernorm_k(
    const float* __restrict__ x, const float* __restrict__ w,
    const float* __restrict__ b, __half* __restrict__ yh, float* __restrict__ yf)
{
    __shared__ float sm1[8], sm2[8];
    ln_row(blockIdx.x, threadIdx.x, x, w, b, yh, yf, sm1, sm2);
}

// ---------------- fp16 mma.sync NT GEMM, 2 CTAs/SM (R9, proven) ----------------
#define NST     3
#define ROWB    144u
#define ATILE_B 18432u
#define ST_BYTE (2u*ATILE_B)
#define GSMEM   (NST*ST_BYTE)          // 110592

template<int EPI>
__global__ void __launch_bounds__(256, 2) gemm_mma(
    const __half* __restrict__ A, const __half* __restrict__ B,
    const float* __restrict__ bias, const float* __restrict__ res,
    void* __restrict__ Cv, int M, int N, int K)
{
    extern __shared__ char smc[];
    const uint32_t smb = smem_u32(smc);
    const int tid  = threadIdx.x;
    const int wid  = tid >> 5;
    const int lane = tid & 31;
    const int g = lane >> 2, c = lane & 3;
    const int wy = wid & 3, wx = wid >> 2;
    const int m0 = blockIdx.y * 128;
    const int n0 = blockIdx.x * 128;
    const int nch = K >> 6;

    const int lr = tid >> 3, lj = tid & 7;
    const __half* asrc0 = A + (size_t)(m0 + lr) * K + lj * 8;
    const __half* bsrc0 = B + (size_t)(n0 + lr) * K + lj * 8;
    const uint32_t adst0 = (uint32_t)lr * ROWB + (uint32_t)lj * 16u;
    const uint32_t bdst0 = ATILE_B + adst0;
    const size_t rstep = (size_t)32 * K;

    #pragma unroll
    for (int p = 0; p < NST - 1; p++) {
        uint32_t sb = smb + p * ST_BYTE;
        #pragma unroll
        for (int i = 0; i < 4; i++) {
            asm volatile("cp.async.cg.shared.global [%0], [%1], 16;"
                :: "r"(sb + adst0 + i*4608u), "l"(asrc0 + i*rstep + p*64));
            asm volatile("cp.async.cg.shared.global [%0], [%1], 16;"
                :: "r"(sb + bdst0 + i*4608u), "l"(bsrc0 + i*rstep + p*64));
        }
        asm volatile("cp.async.commit_group;");
    }

    float acc[2][8][4] = {};
    const uint32_t lrow  = (uint32_t)(lane & 15);
    const uint32_t lhalf = (uint32_t)(lane >> 4);

    for (int ch = 0; ch < nch; ch++) {
        asm volatile("cp.async.wait_group %0;" :: "n"(NST - 2));
        __syncthreads();

        int ch2 = ch + NST - 1;
        if (ch2 < nch) {
            uint32_t sb = smb + (uint32_t)(ch2 % NST) * ST_BYTE;
            #pragma unroll
            for (int i = 0; i < 4; i++) {
                asm volatile("cp.async.cg.shared.global [%0], [%1], 16;"
                    :: "r"(sb + adst0 + i*4608u), "l"(asrc0 + i*rstep + ch2*64));
                asm volatile("cp.async.cg.shared.global [%0], [%1], 16;"
                    :: "r"(sb + bdst0 + i*4608u), "l"(bsrc0 + i*rstep + ch2*64));
            }
        }
        asm volatile("cp.async.commit_group;");

        const uint32_t stb   = smb + (uint32_t)(ch % NST) * ST_BYTE;
        const uint32_t abase = stb + (uint32_t)(wy * 32 + lrow) * ROWB + lhalf * 16u;
        const uint32_t bbase = stb + ATILE_B
                             + (uint32_t)(wx * 64 + lrow) * ROWB + lhalf * 16u;

        #pragma unroll
        for (int ks = 0; ks < 4; ks++) {
            uint32_t koff = (uint32_t)ks * 32u;
            uint32_t af[2][4], bf[8][2];
            #pragma unroll
            for (int mf = 0; mf < 2; mf++)
                ldsm_x4(af[mf], abase + (uint32_t)mf * (16u * ROWB) + koff);
            #pragma unroll
            for (int np = 0; np < 4; np++) {
                uint32_t q[4];
                ldsm_x4(q, bbase + (uint32_t)np * (16u * ROWB) + koff);
                bf[2*np][0]   = q[0]; bf[2*np][1]   = q[2];
                bf[2*np+1][0] = q[1]; bf[2*np+1][1] = q[3];
            }
            #pragma unroll
            for (int mf = 0; mf < 2; mf++)
                #pragma unroll
                for (int nf = 0; nf < 8; nf++)
                    mma_f16(acc[mf][nf], af[mf], bf[nf]);
        }
    }

    const int mbase = m0 + wy * 32;
    const int nbase = n0 + wx * 64;
    #pragma unroll
    for (int mf = 0; mf < 2; mf++) {
        int r0 = mbase + mf * 16 + g;
        #pragma unroll
        for (int nf = 0; nf < 8; nf++) {
            int col = nbase + nf * 8 + c * 2;
            float v0 = acc[mf][nf][0], v1 = acc[mf][nf][1];
            float v2 = acc[mf][nf][2], v3 = acc[mf][nf][3];
            if (EPI >= 1) {
                float b0 = bias[col], b1 = bias[col + 1];
                v0 += b0; v1 += b1; v2 += b0; v3 += b1;
            }
            if (EPI == 1) {
                float* C = (float*)Cv;
                float2 r01 = *(const float2*)(res + (size_t)r0 * N + col);
                float2 r23 = *(const float2*)(res + (size_t)(r0 + 8) * N + col);
                *(float2*)(C + (size_t)r0 * N + col)       = make_float2(v0 + r01.x, v1 + r01.y);
                *(float2*)(C + (size_t)(r0 + 8) * N + col) = make_float2(v2 + r23.x, v3 + r23.y);
            } else {
                if (EPI == 2) {
                    v0 = v0 * normcdff(v0);
                    v1 = v1 * normcdff(v1);
                    v2 = v2 * normcdff(v2);
                    v3 = v3 * normcdff(v3);
                }
                __half* C = (__half*)Cv;
                *(uint32_t*)(C + (size_t)r0 * N + col)       = h2u(__floats2half2_rn(v0, v1));
                *(uint32_t*)(C + (size_t)(r0 + 8) * N + col) = h2u(__floats2half2_rn(v2, v3));
            }
        }
    }
}

// ---------------- Flash attention (R14, proven) ----------------
#define FH_STR 72
#define FH_QS  0
#define FH_K0  (128*FH_STR)
#define FH_V0  (FH_K0 + 3*64*FH_STR)
#define FH_END (FH_V0 + 3*64*FH_STR)        // 36864 halves = 73728 B
#define FSM_TOT (FH_END*2 + 768)
#define FSC   0.18033688f                   // 0.125 * log2(e)
#define FMK  -1.803368801e8f                // -1e9 * 0.125 * log2(e)

__global__ void __launch_bounds__(256, 2) flashm_k(
    const __half* __restrict__ qkv, const int* __restrict__ ids,
    __half* __restrict__ o)
{
    extern __shared__ char smc[];
    __half* smh = (__half*)smc;
    float*  mk  = (float*)(smc + FH_END*2);     // [3][64]
    const uint32_t smb = smem_u32(smc);

    const int tid = threadIdx.x;
    const int wid = tid >> 5, lane = tid & 31;
    const int g = lane >> 2, c = lane & 3;
    const int qt = blockIdx.x, h = blockIdx.y, b = blockIdx.z;
    const int q0 = qt * 128;
    const size_t rstr = 3 * CD;

    const int lr = tid >> 3, lj = tid & 7;
    const uint32_t kvoff = (uint32_t)lr * 144u + (uint32_t)lj * 16u;
    const __half* kvsrc = qkv + ((size_t)(b*CN + lr)) * rstr + CD + h*64 + lj*8;

    // load Q tile
    for (int i = tid; i < 1024; i += 256) {
        int r = i >> 3, j = i & 7;
        *(uint4*)(smh + FH_QS + r * FH_STR + j * 8) =
            *(const uint4*)(qkv + (size_t)(b*CN + q0 + r) * rstr + h*64 + j*8);
    }

    // prologue: async fill stages 0,1 + masks
    #pragma unroll
    for (int p = 0; p < 2; p++) {
        const __half* src = kvsrc + (size_t)(p * 64) * rstr;
        const uint32_t kd0 = smb + (FH_K0 + p*4608)*2 + kvoff;
        const uint32_t vd0 = smb + (FH_V0 + p*4608)*2 + kvoff;
        #pragma unroll
        for (int i = 0; i < 2; i++) {
            asm volatile("cp.async.cg.shared.global [%0], [%1], 16;"
                :: "r"(kd0 + i*4608u), "l"(src + (size_t)i*32*rstr));
            asm volatile("cp.async.cg.shared.global [%0], [%1], 16;"
                :: "r"(vd0 + i*4608u), "l"(src + (size_t)i*32*rstr + CD));
        }
        asm volatile("cp.async.commit_group;");
        if (tid < 64) mk[p*64 + tid] = FMK * (float)ids[b*CN + p*64 + tid];
    }
    __syncthreads();

    // hoist Q fragments
    const uint32_t lrow  = (uint32_t)(lane & 15);
    const uint32_t lhalf = (uint32_t)(lane >> 4);
    uint32_t qf[4][4];
    {
        const uint32_t qbase = smb + (uint32_t)(wid*16 + lrow) * 144u + lhalf * 16u;
        #pragma unroll
        for (int ks = 0; ks < 4; ks++)
            ldsm_x4(qf[ks], qbase + (uint32_t)ks * 32u);
    }

    // hoisted per-stage ldmatrix bases AND cp.async destinations
    uint32_t kb[3], vb[3], kd[3], vd[3];
    #pragma unroll
    for (int s = 0; s < 3; s++) {
        kb[s] = smb + (uint32_t)(FH_K0 + s*4608)*2 + lrow * 144u + lhalf * 16u;
        vb[s] = smb + (uint32_t)(FH_V0 + s*4608)*2 + lrow * 144u + lhalf * 16u;
        kd[s] = smb + (uint32_t)(FH_K0 + s*4608)*2 + kvoff;
        vd[s] = smb + (uint32_t)(FH_V0 + s*4608)*2 + kvoff;
    }

    float oa[8][4] = {};
    float m0 = -1e30f, m1 = -1e30f, l0 = 0.f, l1 = 0.f;

    int st = 0;
    for (int kt = 0; kt < 16; kt++) {
        asm volatile("cp.async.wait_group 1;");
        __syncthreads();

        if (kt < 14) {
            const int s2 = (st + 2 >= 3) ? st - 1 : st + 2;
            const int k2 = (kt + 2) * 64;
            const __half* src = kvsrc + (size_t)k2 * rstr;
            #pragma unroll
            for (int i = 0; i < 2; i++) {
                asm volatile("cp.async.cg.shared.global [%0], [%1], 16;"
                    :: "r"(kd[s2] + i*4608u), "l"(src + (size_t)i*32*rstr));
                asm volatile("cp.async.cg.shared.global [%0], [%1], 16;"
                    :: "r"(vd[s2] + i*4608u), "l"(src + (size_t)i*32*rstr + CD));
            }
            if (tid < 64) mk[s2*64 + tid] = FMK * (float)ids[b*CN + k2 + tid];
        }
        asm volatile("cp.async.commit_group;");

        const uint32_t kbase = kb[st];
        const uint32_t vbase = vb[st];
        const float* mkc = mk + st * 64;

        // ---- S = Q @ K^T ----
        float sa[8][4] = {};
        #pragma unroll
        for (int ks = 0; ks < 4; ks++) {
            #pragma unroll
            for (int np = 0; np < 4; np++) {
                uint32_t q[4];
                ldsm_x4(q, kbase + (uint32_t)np * (16u*144u) + (uint32_t)ks * 32u);
                uint32_t b0[2] = {q[0], q[2]}, b1[2] = {q[1], q[3]};
                mma_f16(sa[2*np],   qf[ks], b0);
                mma_f16(sa[2*np+1], qf[ks], b1);
            }
        }

        // ---- scale+mask (log2 domain) + online softmax via exp2 ----
        float rmax0 = -1e30f, rmax1 = -1e30f;
        #pragma unroll
        for (int nf = 0; nf < 8; nf++) {
            float mv0 = mkc[nf*8 + 2*c], mv1 = mkc[nf*8 + 2*c + 1];
            sa[nf][0] = fmaf(sa[nf][0], FSC, mv0); sa[nf][1] = fmaf(sa[nf][1], FSC, mv1);
            sa[nf][2] = fmaf(sa[nf][2], FSC, mv0); sa[nf][3] = fmaf(sa[nf][3], FSC, mv1);
            rmax0 = fmaxf(rmax0, fmaxf(sa[nf][0], sa[nf][1]));
            rmax1 = fmaxf(rmax1, fmaxf(sa[nf][2], sa[nf][3]));
        }
        rmax0 = fmaxf(rmax0, __shfl_xor_sync(0xffffffffu, rmax0, 1));
        rmax0 = fmaxf(rmax0, __shfl_xor_sync(0xffffffffu, rmax0, 2));
        rmax1 = fmaxf(rmax1, __shfl_xor_sync(0xffffffffu, rmax1, 1));
        rmax1 = fmaxf(rmax1, __shfl_xor_sync(0xffffffffu, rmax1, 2));
        float mn0 = fmaxf(m0, rmax0), mn1 = fmaxf(m1, rmax1);
        float al0 = exp2f(m0 - mn0), al1 = exp2f(m1 - mn1);
        m0 = mn0; m1 = mn1;
        float ps0 = 0.f, ps1 = 0.f;
        #pragma unroll
        for (int nf = 0; nf < 8; nf++) {
            float p0 = exp2f(sa[nf][0] - mn0);
            float p1 = exp2f(sa[nf][1] - mn0);
            float p2 = exp2f(sa[nf][2] - mn1);
            float p3 = exp2f(sa[nf][3] - mn1);
            ps0 += p0 + p1; ps1 += p2 + p3;
            sa[nf][0] = p0; sa[nf][1] = p1; sa[nf][2] = p2; sa[nf][3] = p3;
        }
        ps0 += __shfl_xor_sync(0xffffffffu, ps0, 1);
        ps0 += __shfl_xor_sync(0xffffffffu, ps0, 2);
        ps1 += __shfl_xor_sync(0xffffffffu, ps1, 1);
        ps1 += __shfl_xor_sync(0xffffffffu, ps1, 2);
        l0 = l0 * al0 + ps0;
        l1 = l1 * al1 + ps1;
        #pragma unroll
        for (int nf = 0; nf < 8; nf++) {
            oa[nf][0] *= al0; oa[nf][1] *= al0;
            oa[nf][2] *= al1; oa[nf][3] *= al1;
        }

        // ---- O += P @ V (P A-fragments straight from registers) ----
        #pragma unroll
        for (int ks = 0; ks < 4; ks++) {
            uint32_t a[4];
            a[0] = h2u(__floats2half2_rn(sa[2*ks][0],   sa[2*ks][1]));
            a[1] = h2u(__floats2half2_rn(sa[2*ks][2],   sa[2*ks][3]));
            a[2] = h2u(__floats2half2_rn(sa[2*ks+1][0], sa[2*ks+1][1]));
            a[3] = h2u(__floats2half2_rn(sa[2*ks+1][2], sa[2*ks+1][3]));
            #pragma unroll
            for (int np = 0; np < 4; np++) {
                uint32_t q[4];
                ldsm_x4_t(q, vbase + (uint32_t)ks * (16u*144u) + (uint32_t)np * 32u);
                uint32_t b0[2] = {q[0], q[1]}, b1[2] = {q[2], q[3]};
                mma_f16(oa[2*np],   a, b0);
                mma_f16(oa[2*np+1], a, b1);
            }
        }

        st = (st + 1 >= 3) ? 0 : st + 1;
    }

    // ---- epilogue ----
    float inv0 = 1.0f / l0, inv1 = 1.0f / l1;
    size_t r0 = (size_t)(b*CN + q0 + wid*16 + g) * CD + h*64;
    size_t r1 = (size_t)(b*CN + q0 + wid*16 + g + 8) * CD + h*64;
    #pragma unroll
    for (int nf = 0; nf < 8; nf++) {
        int col = nf*8 + 2*c;
        *(uint32_t*)(o + r0 + col) = h2u(__floats2half2_rn(oa[nf][0]*inv0, oa[nf][1]*inv0));
        *(uint32_t*)(o + r1 + col) = h2u(__floats2half2_rn(oa[nf][2]*inv1, oa[nf][3]*inv1));
    }
}

// ---------------- launch ----------------
extern "C" void kernel_launch(void* const* d_in, const int* in_sizes, int n_in,
                              void* d_out, int out_size)
{
    const float* x      = (const float*)d_in[0];
    const int*   ids    = (const int*)  d_in[1];
    const float* n1w    = (const float*)d_in[2];
    const float* n1b    = (const float*)d_in[3];
    const float* pin_w  = (const float*)d_in[4];
    const float* pout_w = (const float*)d_in[5];
    const float* pout_b = (const float*)d_in[6];
    const float* n2w    = (const float*)d_in[7];
    const float* n2b    = (const float*)d_in[8];
    const float* l1w    = (const float*)d_in[9];
    const float* l1b    = (const float*)d_in[10];
    const float* l2w    = (const float*)d_in[11];
    const float* l2b    = (const float*)d_in[12];
    float* out = (float*)d_out;

    __half *xnh, *qkvh, *aoh, *x2h, *hhh, *wqh, *woh, *w1h, *w2h;
    float *xnf, *x1f, *x2f;
    cudaGetSymbolAddress((void**)&xnh,  g_xn_h);
    cudaGetSymbolAddress((void**)&xnf,  g_xn_f);
    cudaGetSymbolAddress((void**)&qkvh, g_qkv_h);
    cudaGetSymbolAddress((void**)&aoh,  g_ao_h);
    cudaGetSymbolAddress((void**)&x1f,  g_x1_f);
    cudaGetSymbolAddress((void**)&x2h,  g_x2_h);
    cudaGetSymbolAddress((void**)&x2f,  g_x2_f);
    cudaGetSymbolAddress((void**)&hhh,  g_h_h);
    cudaGetSymbolAddress((void**)&wqh,  g_wq_h);
    cudaGetSymbolAddress((void**)&woh,  g_wo_h);
    cudaGetSymbolAddress((void**)&w1h,  g_w1_h);
    cudaGetSymbolAddress((void**)&w2h,  g_w2_h);

    cudaFuncSetAttribute(flashm_k,    cudaFuncAttributeMaxDynamicSharedMemorySize, FSM_TOT);
    cudaFuncSetAttribute(gemm_mma<0>, cudaFuncAttributeMaxDynamicSharedMemorySize, GSMEM);
    cudaFuncSetAttribute(gemm_mma<1>, cudaFuncAttributeMaxDynamicSharedMemorySize, GSMEM);
    cudaFuncSetAttribute(gemm_mma<2>, cudaFuncAttributeMaxDynamicSharedMemorySize, GSMEM);

    // 0+1) fused: LN1 (blocks 0..NTOK-1) + weights->fp16 (remaining blocks)
    ln1_round_k<<<NTOK + NRBLK, 256>>>(
        x, n1w, n1b, xnh, xnf,
        (const float4*)pin_w, (const float4*)pout_w, (const float4*)l1w, (const float4*)l2w,
        (uint2*)wqh, (uint2*)woh, (uint2*)w1h, (uint2*)w2h);

    // 2) qkv = xn @ Wq^T  (fp16 out)
    gemm_mma<0><<<dim3(3*CD/128, NTOK/128), 256, GSMEM>>>(xnh, wqh, nullptr, nullptr, qkvh, NTOK, 3*CD, CD);
    // 3) flash attention -> ao (fp16)
    flashm_k<<<dim3(CN/128, CH, CB), 256, FSM_TOT>>>(qkvh, ids, aoh);
    // 4) x1 = ao @ Wo^T + bout + xn  (fp32 out)
    gemm_mma<1><<<dim3(CD/128, NTOK/128), 256, GSMEM>>>(aoh, woh, pout_b, xnf, x1f, NTOK, CD, CD);
    // 5) x2 = LN2(x1)
    layernorm_k<<<NTOK, 256>>>(x1f, n2w, n2b, x2h, x2f);
    // 6) h = gelu(x2 @ W1^T + b1)  (fp16 out)
    gemm_mma<2><<<dim3(CFF/128, NTOK/128), 256, GSMEM>>>(x2h, w1h, l1b, nullptr, hhh, NTOK, CFF, CD);
    // 7) out = h @ W2^T + b2 + x2  (fp32 out)
    gemm_mma<1><<<dim3(CD/128, NTOK/128), 256, GSMEM>>>(hhh, w2h, l2b, x2f, out, NTOK, CD, CFF);
}